// round 5
// baseline (speedup 1.0000x reference)
#include <cuda_runtime.h>
#include <cuda_bf16.h>
#include <cstdint>
#include <math.h>

#define BATCH 4
#define SEQ   2048
#define HID   768
#define NQKV  (3*HID)
#define TOK   (BATCH*SEQ)   // 8192

// ---------------- scratch (device globals; allocation-free) ----------------
__device__ __align__(128) __nv_bfloat16 g_xhi[(size_t)TOK*HID],  g_xlo[(size_t)TOK*HID];
__device__ __align__(128) __nv_bfloat16 g_whi[(size_t)NQKV*HID], g_wlo[(size_t)NQKV*HID];
__device__ __align__(128) __nv_bfloat16 g_qhi[(size_t)TOK*HID],  g_qlo[(size_t)TOK*HID];
__device__ __align__(128) __nv_bfloat16 g_khi[(size_t)TOK*HID],  g_klo[(size_t)TOK*HID];
__device__ __align__(128) __nv_bfloat16 g_vThi[(size_t)BATCH*HID*SEQ], g_vTlo[(size_t)BATCH*HID*SEQ];
__device__ __align__(128) float g_qf[(size_t)TOK*HID], g_kf[(size_t)TOK*HID], g_vf[(size_t)TOK*HID];
__device__ __align__(128) float         g_scores[(size_t)BATCH*SEQ*SEQ];      // scores, then P (fp32)
__device__ __align__(128) __nv_bfloat16 g_phi[(size_t)BATCH*SEQ*SEQ], g_plo[(size_t)BATCH*SEQ*SEQ];

// ---------------- PTX helpers (sm_80-compatible only) ----------------
__device__ __forceinline__ uint32_t smem_u32(const void* p) {
    uint32_t a;
    asm("{ .reg .u64 t; cvta.to.shared.u64 t, %1; cvt.u32.u64 %0, t; }" : "=r"(a) : "l"(p));
    return a;
}
__device__ __forceinline__ void cp16(uint32_t dst, const void* src) {
    asm volatile("cp.async.cg.shared.global [%0], [%1], 16;" :: "r"(dst), "l"(src));
}
#define CP_COMMIT() asm volatile("cp.async.commit_group;" ::: "memory")
#define CP_WAIT1()  asm volatile("cp.async.wait_group 1;" ::: "memory")

__device__ __forceinline__ void ldm4(uint32_t* r, uint32_t addr) {
    asm volatile("ldmatrix.sync.aligned.m8n8.x4.shared.b16 {%0,%1,%2,%3}, [%4];"
                 : "=r"(r[0]), "=r"(r[1]), "=r"(r[2]), "=r"(r[3]) : "r"(addr));
}
__device__ __forceinline__ void mma16816(float* c, const uint32_t* a, const uint32_t* b) {
    asm volatile("mma.sync.aligned.m16n8k16.row.col.f32.bf16.bf16.f32 "
                 "{%0,%1,%2,%3}, {%4,%5,%6,%7}, {%8,%9}, {%0,%1,%2,%3};"
                 : "+f"(c[0]), "+f"(c[1]), "+f"(c[2]), "+f"(c[3])
                 : "r"(a[0]), "r"(a[1]), "r"(a[2]), "r"(a[3]), "r"(b[0]), "r"(b[1]));
}

// ---------------- hybrid GEMM ----------------------------------------------
// CTAs with bx < nH: HMMA path, 128x128 tile, 3-term bf16 split, 2-stage cp.async.
// CTAs with bx >= nH: FFMA path, 128x64 tile, fp32.
// 256 threads, 2 CTAs/SM co-residency -> tensor + fma pipes run concurrently.
#define ROWB     80
#define TILE_B   (128*ROWB)           // 10240
#define STAGE_B  (4*TILE_B)           // 40960
#define SM_HY    (2*STAGE_B)          // 81920 (2-stage)

#define AS_LD 132
#define BS_LD 68

// EPI: 0 = QKV, 1 = scores, 2 = out.  FT: F-path B is NxK (true) or KxN (false)
template<int EPI, bool FT>
__global__ __launch_bounds__(256, 2)
void hyb_gemm(const __nv_bfloat16* __restrict__ Ahi, const __nv_bfloat16* __restrict__ Alo,
              const __nv_bfloat16* __restrict__ Bhi, const __nv_bfloat16* __restrict__ Blo,
              const float* __restrict__ Af, const float* __restrict__ Bf,
              long long ldaH, long long ldbH, long long ldaF, long long ldbF,
              int K, long long sAH, long long sBH, long long sAF, long long sBF,
              const float* __restrict__ bias, float alpha,
              float* __restrict__ Cf, long long ldc, long long sC, int nH)
{
    extern __shared__ char smem[];
    const int tid = threadIdx.x;
    const int bx = blockIdx.x, by = blockIdx.y, bz = blockIdx.z;

    if (bx < nH) {
        // ================= HMMA path =================
        const uint32_t sbase = smem_u32(smem);
        const int wid = tid >> 5, lane = tid & 31;
        const int wm = wid & 1;          // 2 warps in M (64 rows)
        const int wn = wid >> 1;         // 4 warps in N (32 cols)

        const __nv_bfloat16* a_hi = Ahi + bz * sAH + (long long)by * 128 * ldaH;
        const __nv_bfloat16* a_lo = Alo + bz * sAH + (long long)by * 128 * ldaH;
        const __nv_bfloat16* b_hi = Bhi + bz * sBH + (long long)bx * 128 * ldbH;
        const __nv_bfloat16* b_lo = Blo + bz * sBH + (long long)bx * 128 * ldbH;

        const int m_in = (lane & 7) + 8 * ((lane >> 3) & 1);
        const int kb_a = (lane >> 4) * 16;
        const int n_in = (lane & 7) + 8 * (lane >> 4);
        const int kb_b = ((lane >> 3) & 1) * 16;
        const uint32_t a_row_off = (uint32_t)((wm * 64 + m_in) * ROWB + kb_a);
        const uint32_t b_row_off = (uint32_t)((wn * 32 + n_in) * ROWB + kb_b);

        float acc[4][4][4];
        #pragma unroll
        for (int i = 0; i < 4; i++)
            #pragma unroll
            for (int j = 0; j < 4; j++)
                #pragma unroll
                for (int r = 0; r < 4; r++) acc[i][j][r] = 0.f;

        const int nch = K / 32;

        auto load_stage = [&](int c, int slot) {
            const uint32_t dbase = sbase + (uint32_t)slot * STAGE_B;
            const long long k0 = (long long)c * 32;
            #pragma unroll
            for (int t = 0; t < 4; t++) {
                const __nv_bfloat16* src = (t == 0) ? a_hi : (t == 1) ? a_lo : (t == 2) ? b_hi : b_lo;
                const long long ld = (t < 2) ? ldaH : ldbH;
                #pragma unroll
                for (int p = 0; p < 2; p++) {
                    int idx = tid + p * 256;
                    int r = idx >> 2, ch = idx & 3;
                    cp16(dbase + (uint32_t)(t * TILE_B + r * ROWB + ch * 16),
                         src + (long long)r * ld + k0 + ch * 8);
                }
            }
        };

        load_stage(0, 0); CP_COMMIT();
        load_stage(1, 1); CP_COMMIT();

        for (int c = 0; c < nch; c++) {
            CP_WAIT1();
            __syncthreads();
            const uint32_t st = sbase + (uint32_t)(c & 1) * STAGE_B;
            #pragma unroll
            for (int ks = 0; ks < 2; ks++) {
                uint32_t ah[4][4], al[4][4], bh[2][4], bl[2][4];
                #pragma unroll
                for (int mi = 0; mi < 4; mi++) {
                    uint32_t ao = st + a_row_off + (uint32_t)(mi * 16 * ROWB + ks * 32);
                    ldm4(ah[mi], ao);
                    ldm4(al[mi], ao + TILE_B);
                }
                #pragma unroll
                for (int nj = 0; nj < 2; nj++) {
                    uint32_t bo = st + 2 * TILE_B + b_row_off + (uint32_t)(nj * 16 * ROWB + ks * 32);
                    ldm4(bh[nj], bo);
                    ldm4(bl[nj], bo + TILE_B);
                }
                #pragma unroll
                for (int mi = 0; mi < 4; mi++)
                    #pragma unroll
                    for (int ni = 0; ni < 4; ni++) {
                        const uint32_t* bph = &bh[ni >> 1][(ni & 1) * 2];
                        const uint32_t* bpl = &bl[ni >> 1][(ni & 1) * 2];
                        mma16816(acc[mi][ni], ah[mi], bph);
                        mma16816(acc[mi][ni], ah[mi], bpl);
                        mma16816(acc[mi][ni], al[mi], bph);
                    }
            }
            __syncthreads();
            if (c + 2 < nch) load_stage(c + 2, c & 1);
            CP_COMMIT();
        }

        // ----- H epilogue -----
        const int g = lane >> 2, t4 = lane & 3;
        const int row0 = by * 128 + wm * 64 + g;
        const int col0 = bx * 128 + wn * 32 + t4 * 2;

        if (EPI == 0) {
            const int seg = (bx * 128) / HID;     // 0=Q,1=K,2=V (tile never straddles)
            #pragma unroll
            for (int mi = 0; mi < 4; mi++)
                #pragma unroll
                for (int ni = 0; ni < 4; ni++)
                    #pragma unroll
                    for (int h = 0; h < 2; h++) {
                        long long row = row0 + mi * 16 + h * 8;
                        int col = col0 + ni * 8;
                        float v0 = acc[mi][ni][h * 2 + 0] + bias[col];
                        float v1 = acc[mi][ni][h * 2 + 1] + bias[col + 1];
                        __nv_bfloat16 h0 = __float2bfloat16(v0);
                        __nv_bfloat16 h1 = __float2bfloat16(v1);
                        __nv_bfloat16 l0 = __float2bfloat16(v0 - __bfloat162float(h0));
                        __nv_bfloat16 l1 = __float2bfloat16(v1 - __bfloat162float(h1));
                        if (seg < 2) {
                            int cc = col - seg * HID;
                            __nv_bfloat16* dh = (seg == 0) ? g_qhi : g_khi;
                            __nv_bfloat16* dl = (seg == 0) ? g_qlo : g_klo;
                            float* df = (seg == 0) ? g_qf : g_kf;
                            *reinterpret_cast<__nv_bfloat162*>(dh + row * HID + cc) = __nv_bfloat162(h0, h1);
                            *reinterpret_cast<__nv_bfloat162*>(dl + row * HID + cc) = __nv_bfloat162(l0, l1);
                            *reinterpret_cast<float2*>(df + row * HID + cc) = make_float2(v0, v1);
                        } else {
                            int hh = col - 2 * HID;
                            int b = (int)(row >> 11), s = (int)(row & 2047);
                            size_t o0 = ((size_t)b * HID + hh) * SEQ + s;
                            size_t o1 = o0 + SEQ;
                            g_vThi[o0] = h0; g_vTlo[o0] = l0;
                            g_vThi[o1] = h1; g_vTlo[o1] = l1;
                            *reinterpret_cast<float2*>(g_vf + row * HID + hh) = make_float2(v0, v1);
                        }
                    }
        } else {
            float* cb = Cf + bz * sC;
            #pragma unroll
            for (int mi = 0; mi < 4; mi++)
                #pragma unroll
                for (int ni = 0; ni < 4; ni++)
                    #pragma unroll
                    for (int h = 0; h < 2; h++) {
                        long long row = row0 + mi * 16 + h * 8;
                        int col = col0 + ni * 8;
                        float2 o;
                        o.x = alpha * acc[mi][ni][h * 2 + 0];
                        o.y = alpha * acc[mi][ni][h * 2 + 1];
                        *reinterpret_cast<float2*>(cb + row * ldc + col) = o;
                    }
        }
    } else {
        // ================= FFMA path (128x64, fp32) =================
        float* As = reinterpret_cast<float*>(smem);          // [16][AS_LD]
        float* Bs = As + 16 * AS_LD;                         // [16][BS_LD]
        const int tx = tid & 15;     // 0..15 -> 4 cols each
        const int ty = tid >> 4;     // 0..15 -> 8 rows each

        const int colF0 = nH * 128 + (bx - nH) * 64;
        const float* Ab = Af + bz * sAF + (long long)by * 128 * ldaF;
        const float* Bb = FT ? (Bf + bz * sBF + (long long)colF0 * ldbF)
                             : (Bf + bz * sBF + colF0);

        float acc[8][4];
        #pragma unroll
        for (int i = 0; i < 8; i++)
            #pragma unroll
            for (int j = 0; j < 4; j++) acc[i][j] = 0.f;

        for (int k0 = 0; k0 < K; k0 += 16) {
            // A tile: 128 rows x 16 k, transpose-store
            #pragma unroll
            for (int p = 0; p < 2; p++) {
                int idx = tid + p * 256;
                int r = idx >> 2, kc = (idx & 3) << 2;
                float4 v = *reinterpret_cast<const float4*>(Ab + (long long)r * ldaF + k0 + kc);
                As[(kc + 0) * AS_LD + r] = v.x; As[(kc + 1) * AS_LD + r] = v.y;
                As[(kc + 2) * AS_LD + r] = v.z; As[(kc + 3) * AS_LD + r] = v.w;
            }
            if (FT) {
                int r = tid >> 2, kc = (tid & 3) << 2;       // r: 0..63
                float4 v = *reinterpret_cast<const float4*>(Bb + (long long)r * ldbF + k0 + kc);
                Bs[(kc + 0) * BS_LD + r] = v.x; Bs[(kc + 1) * BS_LD + r] = v.y;
                Bs[(kc + 2) * BS_LD + r] = v.z; Bs[(kc + 3) * BS_LD + r] = v.w;
            } else {
                int kr = tid >> 4, nc = (tid & 15) << 2;     // kr: 0..15
                *reinterpret_cast<float4*>(&Bs[kr * BS_LD + nc]) =
                    *reinterpret_cast<const float4*>(Bb + (long long)(k0 + kr) * ldbF + nc);
            }
            __syncthreads();

            #pragma unroll
            for (int kk = 0; kk < 16; kk++) {
                float a[8], bb[4];
                *reinterpret_cast<float4*>(&a[0]) = *reinterpret_cast<const float4*>(&As[kk * AS_LD + ty * 4]);
                *reinterpret_cast<float4*>(&a[4]) = *reinterpret_cast<const float4*>(&As[kk * AS_LD + ty * 4 + 64]);
                *reinterpret_cast<float4*>(&bb[0]) = *reinterpret_cast<const float4*>(&Bs[kk * BS_LD + tx * 4]);
                #pragma unroll
                for (int i = 0; i < 8; i++)
                    #pragma unroll
                    for (int j = 0; j < 4; j++)
                        acc[i][j] = fmaf(a[i], bb[j], acc[i][j]);
            }
            __syncthreads();
        }

        // ----- F epilogue -----
        if (EPI == 0) {
            // entirely inside V segment
            #pragma unroll
            for (int ih = 0; ih < 2; ih++)
                #pragma unroll
                for (int ii = 0; ii < 4; ii++) {
                    long long row = by * 128 + ty * 4 + ih * 64 + ii;
                    int b = (int)(row >> 11), s = (int)(row & 2047);
                    #pragma unroll
                    for (int jj = 0; jj < 4; jj++) {
                        int c = colF0 + tx * 4 + jj;
                        float v = acc[ih * 4 + ii][jj] + bias[c];
                        int hh = c - 2 * HID;
                        g_vf[row * HID + hh] = v;
                        __nv_bfloat16 hb = __float2bfloat16(v);
                        __nv_bfloat16 lb = __float2bfloat16(v - __bfloat162float(hb));
                        size_t o = ((size_t)b * HID + hh) * SEQ + s;
                        g_vThi[o] = hb; g_vTlo[o] = lb;
                    }
                }
        } else {
            float* cb = Cf + bz * sC;
            #pragma unroll
            for (int ih = 0; ih < 2; ih++)
                #pragma unroll
                for (int ii = 0; ii < 4; ii++) {
                    long long row = by * 128 + ty * 4 + ih * 64 + ii;
                    float4 o;
                    o.x = alpha * acc[ih * 4 + ii][0];
                    o.y = alpha * acc[ih * 4 + ii][1];
                    o.z = alpha * acc[ih * 4 + ii][2];
                    o.w = alpha * acc[ih * 4 + ii][3];
                    *reinterpret_cast<float4*>(cb + row * ldc + colF0 + tx * 4) = o;
                }
        }
    }
}

// ---------------- fp32 -> bf16 hi/lo split ----------------
__global__ __launch_bounds__(256)
void split_f32(const float* __restrict__ x, __nv_bfloat16* __restrict__ hi,
               __nv_bfloat16* __restrict__ lo, int n4)
{
    int i = blockIdx.x * 256 + threadIdx.x;
    if (i >= n4) return;
    float4 v = reinterpret_cast<const float4*>(x)[i];
    __nv_bfloat16 h0 = __float2bfloat16(v.x), h1 = __float2bfloat16(v.y);
    __nv_bfloat16 h2 = __float2bfloat16(v.z), h3 = __float2bfloat16(v.w);
    __nv_bfloat16 l0 = __float2bfloat16(v.x - __bfloat162float(h0));
    __nv_bfloat16 l1 = __float2bfloat16(v.y - __bfloat162float(h1));
    __nv_bfloat16 l2 = __float2bfloat16(v.z - __bfloat162float(h2));
    __nv_bfloat16 l3 = __float2bfloat16(v.w - __bfloat162float(h3));
    reinterpret_cast<__nv_bfloat162*>(hi)[2*i]   = __nv_bfloat162(h0, h1);
    reinterpret_cast<__nv_bfloat162*>(hi)[2*i+1] = __nv_bfloat162(h2, h3);
    reinterpret_cast<__nv_bfloat162*>(lo)[2*i]   = __nv_bfloat162(l0, l1);
    reinterpret_cast<__nv_bfloat162*>(lo)[2*i+1] = __nv_bfloat162(l2, l3);
}

// ------- softmax: fp32 scores -> fp32 P (in place) + bf16 hi/lo probs -------
__global__ __launch_bounds__(256)
void softmax_kernel(float* __restrict__ S, __nv_bfloat16* __restrict__ Phi,
                    __nv_bfloat16* __restrict__ Plo)
{
    __shared__ float red[8];
    float* p = S + (size_t)blockIdx.x * SEQ;
    const int tid = threadIdx.x;

    float v[8];
    float mx = -1e30f;
    #pragma unroll
    for (int i = 0; i < 8; i++) { v[i] = p[tid + i * 256]; mx = fmaxf(mx, v[i]); }
    #pragma unroll
    for (int o = 16; o; o >>= 1) mx = fmaxf(mx, __shfl_xor_sync(0xffffffffu, mx, o));
    if ((tid & 31) == 0) red[tid >> 5] = mx;
    __syncthreads();
    mx = fmaxf(fmaxf(fmaxf(red[0], red[1]), fmaxf(red[2], red[3])),
               fmaxf(fmaxf(red[4], red[5]), fmaxf(red[6], red[7])));

    float sum = 0.f;
    #pragma unroll
    for (int i = 0; i < 8; i++) { v[i] = expf(v[i] - mx); sum += v[i]; }
    #pragma unroll
    for (int o = 16; o; o >>= 1) sum += __shfl_xor_sync(0xffffffffu, sum, o);
    __syncthreads();
    if ((tid & 31) == 0) red[tid >> 5] = sum;
    __syncthreads();
    sum = red[0] + red[1] + red[2] + red[3] + red[4] + red[5] + red[6] + red[7];

    float inv = 1.f / sum;
    __nv_bfloat16* ph = Phi + (size_t)blockIdx.x * SEQ;
    __nv_bfloat16* pl = Plo + (size_t)blockIdx.x * SEQ;
    #pragma unroll
    for (int i = 0; i < 8; i++) {
        float w = v[i] * inv;
        p[tid + i * 256] = w;                        // fp32 P for FFMA path
        __nv_bfloat16 h = __float2bfloat16(w);
        __nv_bfloat16 l = __float2bfloat16(w - __bfloat162float(h));
        ph[tid + i * 256] = h;
        pl[tid + i * 256] = l;
    }
}

// ---------------------------------------------------------------------------
extern "C" void kernel_launch(void* const* d_in, const int* in_sizes, int n_in,
                              void* d_out, int out_size)
{
    const float* X = (const float*)d_in[0];
    const float* W = (const float*)d_in[1];
    const float* b = (const float*)d_in[2];
    float* out = (float*)d_out;

    static bool attr_set = false;
    if (!attr_set) {
        cudaFuncSetAttribute((const void*)hyb_gemm<0,true>,  cudaFuncAttributeMaxDynamicSharedMemorySize, SM_HY);
        cudaFuncSetAttribute((const void*)hyb_gemm<1,true>,  cudaFuncAttributeMaxDynamicSharedMemorySize, SM_HY);
        cudaFuncSetAttribute((const void*)hyb_gemm<2,false>, cudaFuncAttributeMaxDynamicSharedMemorySize, SM_HY);
        attr_set = true;
    }

    void *xhi, *xlo, *whi, *wlo, *qhi, *qlo, *khi, *klo, *vThi, *vTlo;
    void *qf, *kf, *vf, *sc, *phi, *plo;
    cudaGetSymbolAddress(&xhi, g_xhi);   cudaGetSymbolAddress(&xlo, g_xlo);
    cudaGetSymbolAddress(&whi, g_whi);   cudaGetSymbolAddress(&wlo, g_wlo);
    cudaGetSymbolAddress(&qhi, g_qhi);   cudaGetSymbolAddress(&qlo, g_qlo);
    cudaGetSymbolAddress(&khi, g_khi);   cudaGetSymbolAddress(&klo, g_klo);
    cudaGetSymbolAddress(&vThi, g_vThi); cudaGetSymbolAddress(&vTlo, g_vTlo);
    cudaGetSymbolAddress(&qf, g_qf);     cudaGetSymbolAddress(&kf, g_kf);
    cudaGetSymbolAddress(&vf, g_vf);
    cudaGetSymbolAddress(&sc, g_scores);
    cudaGetSymbolAddress(&phi, g_phi);   cudaGetSymbolAddress(&plo, g_plo);

    // 1) split inputs to bf16 hi/lo
    split_f32<<<(TOK * HID / 4 + 255) / 256, 256>>>(X, (__nv_bfloat16*)xhi, (__nv_bfloat16*)xlo, TOK * HID / 4);
    split_f32<<<(NQKV * HID / 4 + 255) / 256, 256>>>(W, (__nv_bfloat16*)whi, (__nv_bfloat16*)wlo, NQKV * HID / 4);

    // 2) QKV (M=8192, N=2304, K=768): H tiles cols [0,1664), F cols [1664,2304)
    hyb_gemm<0,true><<<dim3(13 + 10, TOK / 128, 1), 256, SM_HY>>>(
        (__nv_bfloat16*)xhi, (__nv_bfloat16*)xlo, (__nv_bfloat16*)whi, (__nv_bfloat16*)wlo,
        X, W,
        HID, HID, HID, HID, HID,
        0LL, 0LL, 0LL, 0LL,
        b, 1.0f, nullptr, 0LL, 0LL, 13);

    // 3) scores (M=N=2048, K=768): H cols [0,1536), F cols [1536,2048)
    hyb_gemm<1,true><<<dim3(12 + 8, SEQ / 128, BATCH), 256, SM_HY>>>(
        (__nv_bfloat16*)qhi, (__nv_bfloat16*)qlo, (__nv_bfloat16*)khi, (__nv_bfloat16*)klo,
        (const float*)qf, (const float*)kf,
        HID, HID, HID, HID, HID,
        (long long)SEQ * HID, (long long)SEQ * HID, (long long)SEQ * HID, (long long)SEQ * HID,
        nullptr, rsqrtf((float)HID), (float*)sc, SEQ, (long long)SEQ * SEQ, 12);

    // 4) softmax -> fp32 P in place + bf16 hi/lo
    softmax_kernel<<<BATCH * SEQ, 256>>>((float*)sc, (__nv_bfloat16*)phi, (__nv_bfloat16*)plo);

    // 5) out = P @ V (M=2048, N=768, K=2048): H cols [0,512), F cols [512,768)
    hyb_gemm<2,false><<<dim3(4 + 4, SEQ / 128, BATCH), 256, SM_HY>>>(
        (__nv_bfloat16*)phi, (__nv_bfloat16*)plo, (__nv_bfloat16*)vThi, (__nv_bfloat16*)vTlo,
        (const float*)sc, (const float*)vf,
        SEQ, SEQ, SEQ, HID, SEQ,
        (long long)SEQ * SEQ, (long long)HID * SEQ, (long long)SEQ * SEQ, (long long)SEQ * HID,
        nullptr, 1.0f, out, HID, (long long)SEQ * HID, 4);
}

// round 6
// speedup vs baseline: 2.0640x; 2.0640x over previous
#include <cuda_runtime.h>
#include <cuda_fp16.h>
#include <cstdint>
#include <math.h>

#define BATCH 4
#define SEQ   2048
#define HID   768
#define NQKV  (3*HID)
#define TOK   (BATCH*SEQ)   // 8192

// ---------------- scratch (device globals; allocation-free) ----------------
__device__ __align__(128) __half g_xhi[(size_t)TOK*HID], g_xlo[(size_t)TOK*HID];
__device__ __align__(128) __half g_wh [(size_t)NQKV*HID];
__device__ __align__(128) __half g_qhi[(size_t)TOK*HID], g_qlo[(size_t)TOK*HID];
__device__ __align__(128) __half g_kh [(size_t)TOK*HID];
__device__ __align__(128) __half g_vTh[(size_t)BATCH*HID*SEQ];
__device__ __align__(128) float  g_scores[(size_t)BATCH*SEQ*SEQ];
__device__ __align__(128) __half g_phi[(size_t)BATCH*SEQ*SEQ], g_plo[(size_t)BATCH*SEQ*SEQ];

// ---------------- PTX helpers (sm_80-compatible only) ----------------
__device__ __forceinline__ uint32_t smem_u32(const void* p) {
    uint32_t a;
    asm("{ .reg .u64 t; cvta.to.shared.u64 t, %1; cvt.u32.u64 %0, t; }" : "=r"(a) : "l"(p));
    return a;
}
__device__ __forceinline__ void cp16(uint32_t dst, const void* src) {
    asm volatile("cp.async.cg.shared.global [%0], [%1], 16;" :: "r"(dst), "l"(src));
}
#define CP_COMMIT() asm volatile("cp.async.commit_group;" ::: "memory")
#define CP_WAIT1()  asm volatile("cp.async.wait_group 1;" ::: "memory")

__device__ __forceinline__ void ldm4(uint32_t* r, uint32_t addr) {
    asm volatile("ldmatrix.sync.aligned.m8n8.x4.shared.b16 {%0,%1,%2,%3}, [%4];"
                 : "=r"(r[0]), "=r"(r[1]), "=r"(r[2]), "=r"(r[3]) : "r"(addr));
}
__device__ __forceinline__ void mma16816(float* c, const uint32_t* a, const uint32_t* b) {
    asm volatile("mma.sync.aligned.m16n8k16.row.col.f32.f16.f16.f32 "
                 "{%0,%1,%2,%3}, {%4,%5,%6,%7}, {%8,%9}, {%0,%1,%2,%3};"
                 : "+f"(c[0]), "+f"(c[1]), "+f"(c[2]), "+f"(c[3])
                 : "r"(a[0]), "r"(a[1]), "r"(a[2]), "r"(a[3]), "r"(b[0]), "r"(b[1]));
}

// -------- HMMA GEMM: C[128x128] = (Ahi+Alo)(MxK) · Bh(NxK)^T  (fp16 2-term) --
// SMEM tile: 128 rows x 32 fp16 padded to 80B/row. 3 tiles/stage, 3 stages.
#define ROWB    80
#define TILE_B  (128*ROWB)          // 10240
#define STAGE_B (3*TILE_B)          // 30720
#define NSTAGE  3
#define SM_TOTAL (NSTAGE*STAGE_B)   // 92160

#define OFF_AHI 0
#define OFF_ALO TILE_B
#define OFF_BH  (2*TILE_B)

// EPI: 0 = QKV (bias; Q->split, K->fp16, V->fp16 transposed), 1/2 = f32 out*alpha
template<int EPI>
__global__ __launch_bounds__(256, 1)
void hmma_gemm(const __half* __restrict__ Ahi, const __half* __restrict__ Alo,
               const __half* __restrict__ Bh,
               long long lda, long long ldb, int K,
               long long sA, long long sB,
               const float* __restrict__ bias, float alpha,
               float* __restrict__ Cf, long long ldc, long long sC)
{
    extern __shared__ char smem[];
    const uint32_t sbase = smem_u32(smem);
    const int tid = threadIdx.x;
    const int bx = blockIdx.x, by = blockIdx.y, bz = blockIdx.z;
    const int wid = tid >> 5, lane = tid & 31;
    const int wm = wid & 1;          // 2 warps in M (64 rows each)
    const int wn = wid >> 1;         // 4 warps in N (32 cols each)

    const __half* a_hi = Ahi + bz * sA + (long long)by * 128 * lda;
    const __half* a_lo = Alo + bz * sA + (long long)by * 128 * lda;
    const __half* b_h  = Bh  + bz * sB + (long long)bx * 128 * ldb;

    // per-thread ldmatrix lane addressing
    const int m_in = (lane & 7) + 8 * ((lane >> 3) & 1);
    const int kb_a = (lane >> 4) * 16;
    const int n_in = (lane & 7) + 8 * (lane >> 4);
    const int kb_b = ((lane >> 3) & 1) * 16;
    const uint32_t a_row_off = (uint32_t)((wm * 64 + m_in) * ROWB + kb_a);
    const uint32_t b_row_off = (uint32_t)((wn * 32 + n_in) * ROWB + kb_b);

    float acc[4][4][4];
    #pragma unroll
    for (int i = 0; i < 4; i++)
        #pragma unroll
        for (int j = 0; j < 4; j++)
            #pragma unroll
            for (int r = 0; r < 4; r++) acc[i][j][r] = 0.f;

    const int nch = K / 32;

    // stage loader: 3 tiles x 512 cp16 slots / 256 threads = 6 cp16/thread
    auto load_stage = [&](int c, int slot) {
        const uint32_t dbase = sbase + (uint32_t)slot * STAGE_B;
        const long long k0 = (long long)c * 32;
        #pragma unroll
        for (int t = 0; t < 3; t++) {
            const __half* src = (t == 0) ? a_hi : (t == 1) ? a_lo : b_h;
            const long long ld = (t < 2) ? lda : ldb;
            #pragma unroll
            for (int p = 0; p < 2; p++) {
                int idx = tid + p * 256;        // 0..511
                int r = idx >> 2, ch = idx & 3;
                cp16(dbase + (uint32_t)(t * TILE_B + r * ROWB + ch * 16),
                     src + (long long)r * ld + k0 + ch * 8);
            }
        }
    };

    load_stage(0, 0); CP_COMMIT();
    load_stage(1, 1); CP_COMMIT();

    for (int c = 0; c < nch; c++) {
        CP_WAIT1();
        __syncthreads();
        if (c + 2 < nch) load_stage(c + 2, (c + 2) % NSTAGE);
        CP_COMMIT();

        const uint32_t st = sbase + (uint32_t)(c % NSTAGE) * STAGE_B;
        #pragma unroll
        for (int ks = 0; ks < 2; ks++) {
            uint32_t ah[4][4], al[4][4], bh[2][4];
            #pragma unroll
            for (int mi = 0; mi < 4; mi++) {
                uint32_t ao = st + a_row_off + (uint32_t)(mi * 16 * ROWB + ks * 32);
                ldm4(ah[mi], ao + OFF_AHI);
                ldm4(al[mi], ao + OFF_ALO);
            }
            #pragma unroll
            for (int nj = 0; nj < 2; nj++) {
                uint32_t bo = st + OFF_BH + b_row_off + (uint32_t)(nj * 16 * ROWB + ks * 32);
                ldm4(bh[nj], bo);
            }
            // term-major: each acc's 2 updates are 16 MMAs apart
            #pragma unroll
            for (int mi = 0; mi < 4; mi++)
                #pragma unroll
                for (int ni = 0; ni < 4; ni++)
                    mma16816(acc[mi][ni], ah[mi], &bh[ni >> 1][(ni & 1) * 2]);
            #pragma unroll
            for (int mi = 0; mi < 4; mi++)
                #pragma unroll
                for (int ni = 0; ni < 4; ni++)
                    mma16816(acc[mi][ni], al[mi], &bh[ni >> 1][(ni & 1) * 2]);
        }
    }

    // ---------------- epilogue ----------------
    const int g = lane >> 2, t4 = lane & 3;
    const int row0 = by * 128 + wm * 64 + g;
    const int col0 = bx * 128 + wn * 32 + t4 * 2;

    if (EPI == 0) {
        const int seg = (bx * 128) / HID;          // 0=Q, 1=K, 2=V (tile never straddles)
        #pragma unroll
        for (int mi = 0; mi < 4; mi++)
            #pragma unroll
            for (int ni = 0; ni < 4; ni++)
                #pragma unroll
                for (int h = 0; h < 2; h++) {      // row halves (regs {0,1} vs {2,3})
                    long long row = row0 + mi * 16 + h * 8;
                    int col = col0 + ni * 8;
                    float v0 = acc[mi][ni][h * 2 + 0] + bias[col];
                    float v1 = acc[mi][ni][h * 2 + 1] + bias[col + 1];
                    __half h0 = __float2half_rn(v0);
                    __half h1 = __float2half_rn(v1);
                    if (seg == 0) {
                        int cc = col;
                        __half l0 = __float2half_rn(v0 - __half2float(h0));
                        __half l1 = __float2half_rn(v1 - __half2float(h1));
                        *reinterpret_cast<__half2*>(g_qhi + row * HID + cc) = __half2(h0, h1);
                        *reinterpret_cast<__half2*>(g_qlo + row * HID + cc) = __half2(l0, l1);
                    } else if (seg == 1) {
                        int cc = col - HID;
                        *reinterpret_cast<__half2*>(g_kh + row * HID + cc) = __half2(h0, h1);
                    } else {
                        int hh = col - 2 * HID;
                        int b = (int)(row >> 11), s = (int)(row & 2047);
                        size_t o0 = ((size_t)b * HID + hh) * SEQ + s;
                        g_vTh[o0] = h0;
                        g_vTh[o0 + SEQ] = h1;
                    }
                }
    } else {
        float* cb = Cf + bz * sC;
        #pragma unroll
        for (int mi = 0; mi < 4; mi++)
            #pragma unroll
            for (int ni = 0; ni < 4; ni++)
                #pragma unroll
                for (int h = 0; h < 2; h++) {
                    long long row = row0 + mi * 16 + h * 8;
                    int col = col0 + ni * 8;
                    float2 o;
                    o.x = alpha * acc[mi][ni][h * 2 + 0];
                    o.y = alpha * acc[mi][ni][h * 2 + 1];
                    *reinterpret_cast<float2*>(cb + row * ldc + col) = o;
                }
    }
}

// ---------------- fp32 -> fp16 hi/lo split ----------------
__global__ __launch_bounds__(256)
void split_f32(const float* __restrict__ x, __half* __restrict__ hi,
               __half* __restrict__ lo, int n4)
{
    int i = blockIdx.x * 256 + threadIdx.x;
    if (i >= n4) return;
    float4 v = reinterpret_cast<const float4*>(x)[i];
    __half h0 = __float2half_rn(v.x), h1 = __float2half_rn(v.y);
    __half h2 = __float2half_rn(v.z), h3 = __float2half_rn(v.w);
    __half l0 = __float2half_rn(v.x - __half2float(h0));
    __half l1 = __float2half_rn(v.y - __half2float(h1));
    __half l2 = __float2half_rn(v.z - __half2float(h2));
    __half l3 = __float2half_rn(v.w - __half2float(h3));
    reinterpret_cast<__half2*>(hi)[2*i]   = __half2(h0, h1);
    reinterpret_cast<__half2*>(hi)[2*i+1] = __half2(h2, h3);
    reinterpret_cast<__half2*>(lo)[2*i]   = __half2(l0, l1);
    reinterpret_cast<__half2*>(lo)[2*i+1] = __half2(l2, l3);
}

// ---------------- fp32 -> fp16 truncate (for W) ----------------
__global__ __launch_bounds__(256)
void cvt_f32(const float* __restrict__ x, __half* __restrict__ h, int n4)
{
    int i = blockIdx.x * 256 + threadIdx.x;
    if (i >= n4) return;
    float4 v = reinterpret_cast<const float4*>(x)[i];
    reinterpret_cast<__half2*>(h)[2*i]   = __half2(__float2half_rn(v.x), __float2half_rn(v.y));
    reinterpret_cast<__half2*>(h)[2*i+1] = __half2(__float2half_rn(v.z), __float2half_rn(v.w));
}

// ---------------- softmax: fp32 scores -> fp16 hi/lo probs ----------------
__global__ __launch_bounds__(256)
void softmax_kernel(const float* __restrict__ S, __half* __restrict__ Phi,
                    __half* __restrict__ Plo)
{
    __shared__ float red[8];
    const float* p = S + (size_t)blockIdx.x * SEQ;
    const int tid = threadIdx.x;

    float v[8];
    float mx = -1e30f;
    #pragma unroll
    for (int i = 0; i < 8; i++) { v[i] = p[tid + i * 256]; mx = fmaxf(mx, v[i]); }
    #pragma unroll
    for (int o = 16; o; o >>= 1) mx = fmaxf(mx, __shfl_xor_sync(0xffffffffu, mx, o));
    if ((tid & 31) == 0) red[tid >> 5] = mx;
    __syncthreads();
    mx = fmaxf(fmaxf(fmaxf(red[0], red[1]), fmaxf(red[2], red[3])),
               fmaxf(fmaxf(red[4], red[5]), fmaxf(red[6], red[7])));

    float sum = 0.f;
    #pragma unroll
    for (int i = 0; i < 8; i++) { v[i] = expf(v[i] - mx); sum += v[i]; }
    #pragma unroll
    for (int o = 16; o; o >>= 1) sum += __shfl_xor_sync(0xffffffffu, sum, o);
    __syncthreads();
    if ((tid & 31) == 0) red[tid >> 5] = sum;
    __syncthreads();
    sum = red[0] + red[1] + red[2] + red[3] + red[4] + red[5] + red[6] + red[7];

    float inv = 1.f / sum;
    __half* ph = Phi + (size_t)blockIdx.x * SEQ;
    __half* pl = Plo + (size_t)blockIdx.x * SEQ;
    #pragma unroll
    for (int i = 0; i < 8; i++) {
        float w = v[i] * inv;
        __half h = __float2half_rn(w);
        __half l = __float2half_rn(w - __half2float(h));
        ph[tid + i * 256] = h;
        pl[tid + i * 256] = l;
    }
}

// ---------------------------------------------------------------------------
extern "C" void kernel_launch(void* const* d_in, const int* in_sizes, int n_in,
                              void* d_out, int out_size)
{
    const float* X = (const float*)d_in[0];
    const float* W = (const float*)d_in[1];
    const float* b = (const float*)d_in[2];
    float* out = (float*)d_out;

    static bool attr_set = false;
    if (!attr_set) {
        cudaFuncSetAttribute(hmma_gemm<0>, cudaFuncAttributeMaxDynamicSharedMemorySize, SM_TOTAL);
        cudaFuncSetAttribute(hmma_gemm<1>, cudaFuncAttributeMaxDynamicSharedMemorySize, SM_TOTAL);
        cudaFuncSetAttribute(hmma_gemm<2>, cudaFuncAttributeMaxDynamicSharedMemorySize, SM_TOTAL);
        attr_set = true;
    }

    void *xhi, *xlo, *wh, *qhi, *qlo, *kh, *vTh, *sc, *phi, *plo;
    cudaGetSymbolAddress(&xhi, g_xhi); cudaGetSymbolAddress(&xlo, g_xlo);
    cudaGetSymbolAddress(&wh, g_wh);
    cudaGetSymbolAddress(&qhi, g_qhi); cudaGetSymbolAddress(&qlo, g_qlo);
    cudaGetSymbolAddress(&kh, g_kh);   cudaGetSymbolAddress(&vTh, g_vTh);
    cudaGetSymbolAddress(&sc, g_scores);
    cudaGetSymbolAddress(&phi, g_phi); cudaGetSymbolAddress(&plo, g_plo);

    // 1) convert inputs: X split hi/lo, W truncated
    split_f32<<<(TOK * HID / 4 + 255) / 256, 256>>>(X, (__half*)xhi, (__half*)xlo, TOK * HID / 4);
    cvt_f32<<<(NQKV * HID / 4 + 255) / 256, 256>>>(W, (__half*)wh, NQKV * HID / 4);

    // 2) QKV = X @ W^T + b  (M=8192, N=2304, K=768)
    hmma_gemm<0><<<dim3(NQKV / 128, TOK / 128, 1), 256, SM_TOTAL>>>(
        (__half*)xhi, (__half*)xlo, (__half*)wh,
        HID, HID, HID, 0LL, 0LL, b, 1.0f, nullptr, 0LL, 0LL);

    // 3) scores = (Q @ K^T) / sqrt(768)  per batch (M=N=2048, K=768)
    hmma_gemm<1><<<dim3(SEQ / 128, SEQ / 128, BATCH), 256, SM_TOTAL>>>(
        (__half*)qhi, (__half*)qlo, (__half*)kh,
        HID, HID, HID, (long long)SEQ * HID, (long long)SEQ * HID,
        nullptr, rsqrtf((float)HID), (float*)sc, SEQ, (long long)SEQ * SEQ);

    // 4) softmax -> fp16 hi/lo probs
    softmax_kernel<<<BATCH * SEQ, 256>>>((const float*)sc, (__half*)phi, (__half*)plo);

    // 5) out = P @ V  per batch (M=2048, N=768, K=2048); B = vT (NT layout)
    hmma_gemm<2><<<dim3(HID / 128, SEQ / 128, BATCH), 256, SM_TOTAL>>>(
        (__half*)phi, (__half*)plo, (__half*)vTh,
        SEQ, SEQ, SEQ, (long long)SEQ * SEQ, (long long)HID * SEQ,
        nullptr, 1.0f, out, HID, (long long)SEQ * HID);
}

// round 7
// speedup vs baseline: 2.3401x; 1.1338x over previous
#include <cuda_runtime.h>
#include <cuda_fp16.h>
#include <cstdint>
#include <math.h>

#define BATCH 4
#define SEQ   2048
#define HID   768
#define NQKV  (3*HID)
#define TOK   (BATCH*SEQ)   // 8192

// ---------------- scratch (device globals; allocation-free) ----------------
__device__ __align__(128) __half g_xh [(size_t)TOK*HID];
__device__ __align__(128) __half g_wh [(size_t)NQKV*HID];
__device__ __align__(128) __half g_qhi[(size_t)TOK*HID], g_qlo[(size_t)TOK*HID];
__device__ __align__(128) __half g_kh [(size_t)TOK*HID];
__device__ __align__(128) __half g_vTh[(size_t)BATCH*HID*SEQ];
__device__ __align__(128) float  g_scores[(size_t)BATCH*SEQ*SEQ];
__device__ __align__(128) __half g_phi[(size_t)BATCH*SEQ*SEQ], g_plo[(size_t)BATCH*SEQ*SEQ];

// ---------------- PTX helpers (sm_80-compatible only) ----------------
__device__ __forceinline__ uint32_t smem_u32(const void* p) {
    uint32_t a;
    asm("{ .reg .u64 t; cvta.to.shared.u64 t, %1; cvt.u32.u64 %0, t; }" : "=r"(a) : "l"(p));
    return a;
}
__device__ __forceinline__ void cp16(uint32_t dst, const void* src) {
    asm volatile("cp.async.cg.shared.global [%0], [%1], 16;" :: "r"(dst), "l"(src));
}
#define CP_COMMIT() asm volatile("cp.async.commit_group;" ::: "memory")
#define CP_WAIT1()  asm volatile("cp.async.wait_group 1;" ::: "memory")

__device__ __forceinline__ void ldm4(uint32_t* r, uint32_t addr) {
    asm volatile("ldmatrix.sync.aligned.m8n8.x4.shared.b16 {%0,%1,%2,%3}, [%4];"
                 : "=r"(r[0]), "=r"(r[1]), "=r"(r[2]), "=r"(r[3]) : "r"(addr));
}
__device__ __forceinline__ void mma16816(float* c, const uint32_t* a, const uint32_t* b) {
    asm volatile("mma.sync.aligned.m16n8k16.row.col.f32.f16.f16.f32 "
                 "{%0,%1,%2,%3}, {%4,%5,%6,%7}, {%8,%9}, {%0,%1,%2,%3};"
                 : "+f"(c[0]), "+f"(c[1]), "+f"(c[2]), "+f"(c[3])
                 : "r"(a[0]), "r"(a[1]), "r"(a[2]), "r"(a[3]), "r"(b[0]), "r"(b[1]));
}

// -------- HMMA GEMM: C[128x128] = (A or Ahi+Alo)(MxK) · Bh(NxK)^T -----------
// SMEM tile: 128 rows x 32 fp16 padded to 80B/row. (NTERM+1) tiles/stage, 3 stages.
#define ROWB    80
#define TILE_B  (128*ROWB)          // 10240
#define NSTAGE  3

// EPI: 0 = QKV (bias; Q->split, K->fp16, V->fp16 transposed), 1/2 = f32 out*alpha
template<int EPI, int NTERM>
__global__ __launch_bounds__(256, 1)
void hmma_gemm(const __half* __restrict__ Ahi, const __half* __restrict__ Alo,
               const __half* __restrict__ Bh,
               long long lda, long long ldb, int K,
               long long sA, long long sB,
               const float* __restrict__ bias, float alpha,
               float* __restrict__ Cf, long long ldc, long long sC)
{
    constexpr int NTILE   = NTERM + 1;
    constexpr int STAGE_B = NTILE * TILE_B;
    constexpr int OFF_BH  = NTERM * TILE_B;

    extern __shared__ char smem[];
    const uint32_t sbase = smem_u32(smem);
    const int tid = threadIdx.x;
    const int bx = blockIdx.x, by = blockIdx.y, bz = blockIdx.z;
    const int wid = tid >> 5, lane = tid & 31;
    const int wm = wid & 1;          // 2 warps in M (64 rows each)
    const int wn = wid >> 1;         // 4 warps in N (32 cols each)

    const __half* a_hi = Ahi + bz * sA + (long long)by * 128 * lda;
    const __half* a_lo = (NTERM == 2) ? (Alo + bz * sA + (long long)by * 128 * lda) : nullptr;
    const __half* b_h  = Bh  + bz * sB + (long long)bx * 128 * ldb;

    // per-thread ldmatrix lane addressing
    const int m_in = (lane & 7) + 8 * ((lane >> 3) & 1);
    const int kb_a = (lane >> 4) * 16;
    const int n_in = (lane & 7) + 8 * (lane >> 4);
    const int kb_b = ((lane >> 3) & 1) * 16;
    const uint32_t a_row_off = (uint32_t)((wm * 64 + m_in) * ROWB + kb_a);
    const uint32_t b_row_off = (uint32_t)((wn * 32 + n_in) * ROWB + kb_b);

    float acc[4][4][4];
    #pragma unroll
    for (int i = 0; i < 4; i++)
        #pragma unroll
        for (int j = 0; j < 4; j++)
            #pragma unroll
            for (int r = 0; r < 4; r++) acc[i][j][r] = 0.f;

    const int nch = K / 32;

    auto load_stage = [&](int c, int slot) {
        const uint32_t dbase = sbase + (uint32_t)slot * STAGE_B;
        const long long k0 = (long long)c * 32;
        #pragma unroll
        for (int t = 0; t < NTILE; t++) {
            const __half* src = (t == NTERM) ? b_h : (t == 0 ? a_hi : a_lo);
            const long long ld = (t == NTERM) ? ldb : lda;
            #pragma unroll
            for (int p = 0; p < 2; p++) {
                int idx = tid + p * 256;        // 0..511
                int r = idx >> 2, ch = idx & 3;
                cp16(dbase + (uint32_t)(t * TILE_B + r * ROWB + ch * 16),
                     src + (long long)r * ld + k0 + ch * 8);
            }
        }
    };

    load_stage(0, 0); CP_COMMIT();
    load_stage(1, 1); CP_COMMIT();

    for (int c = 0; c < nch; c++) {
        CP_WAIT1();
        __syncthreads();
        if (c + 2 < nch) load_stage(c + 2, (c + 2) % NSTAGE);
        CP_COMMIT();

        const uint32_t st = sbase + (uint32_t)(c % NSTAGE) * STAGE_B;
        #pragma unroll
        for (int ks = 0; ks < 2; ks++) {
            uint32_t ah[4][4], al[4][4], bh[2][4];
            #pragma unroll
            for (int mi = 0; mi < 4; mi++) {
                uint32_t ao = st + a_row_off + (uint32_t)(mi * 16 * ROWB + ks * 32);
                ldm4(ah[mi], ao);
                if (NTERM == 2) ldm4(al[mi], ao + TILE_B);
            }
            #pragma unroll
            for (int nj = 0; nj < 2; nj++) {
                uint32_t bo = st + OFF_BH + b_row_off + (uint32_t)(nj * 16 * ROWB + ks * 32);
                ldm4(bh[nj], bo);
            }
            #pragma unroll
            for (int mi = 0; mi < 4; mi++)
                #pragma unroll
                for (int ni = 0; ni < 4; ni++)
                    mma16816(acc[mi][ni], ah[mi], &bh[ni >> 1][(ni & 1) * 2]);
            if (NTERM == 2) {
                #pragma unroll
                for (int mi = 0; mi < 4; mi++)
                    #pragma unroll
                    for (int ni = 0; ni < 4; ni++)
                        mma16816(acc[mi][ni], al[mi], &bh[ni >> 1][(ni & 1) * 2]);
            }
        }
    }

    // ---------------- epilogue ----------------
    const int g = lane >> 2, t4 = lane & 3;
    const int row0 = by * 128 + wm * 64 + g;
    const int col0 = bx * 128 + wn * 32 + t4 * 2;

    if (EPI == 0) {
        const int seg = (bx * 128) / HID;          // 0=Q, 1=K, 2=V (tile never straddles)
        #pragma unroll
        for (int mi = 0; mi < 4; mi++)
            #pragma unroll
            for (int ni = 0; ni < 4; ni++)
                #pragma unroll
                for (int h = 0; h < 2; h++) {      // row halves (regs {0,1} vs {2,3})
                    long long row = row0 + mi * 16 + h * 8;
                    int col = col0 + ni * 8;
                    float v0 = acc[mi][ni][h * 2 + 0] + bias[col];
                    float v1 = acc[mi][ni][h * 2 + 1] + bias[col + 1];
                    __half h0 = __float2half_rn(v0);
                    __half h1 = __float2half_rn(v1);
                    if (seg == 0) {
                        int cc = col;
                        __half l0 = __float2half_rn(v0 - __half2float(h0));
                        __half l1 = __float2half_rn(v1 - __half2float(h1));
                        *reinterpret_cast<__half2*>(g_qhi + row * HID + cc) = __half2(h0, h1);
                        *reinterpret_cast<__half2*>(g_qlo + row * HID + cc) = __half2(l0, l1);
                    } else if (seg == 1) {
                        int cc = col - HID;
                        *reinterpret_cast<__half2*>(g_kh + row * HID + cc) = __half2(h0, h1);
                    } else {
                        int hh = col - 2 * HID;
                        int b = (int)(row >> 11), s = (int)(row & 2047);
                        size_t o0 = ((size_t)b * HID + hh) * SEQ + s;
                        g_vTh[o0] = h0;
                        g_vTh[o0 + SEQ] = h1;
                    }
                }
    } else {
        float* cb = Cf + bz * sC;
        #pragma unroll
        for (int mi = 0; mi < 4; mi++)
            #pragma unroll
            for (int ni = 0; ni < 4; ni++)
                #pragma unroll
                for (int h = 0; h < 2; h++) {
                    long long row = row0 + mi * 16 + h * 8;
                    int col = col0 + ni * 8;
                    float2 o;
                    o.x = alpha * acc[mi][ni][h * 2 + 0];
                    o.y = alpha * acc[mi][ni][h * 2 + 1];
                    *reinterpret_cast<float2*>(cb + row * ldc + col) = o;
                }
    }
}

// ---------------- fp32 -> fp16 truncate ----------------
__global__ __launch_bounds__(256)
void cvt_f32(const float* __restrict__ x, __half* __restrict__ h, int n4)
{
    int i = blockIdx.x * 256 + threadIdx.x;
    if (i >= n4) return;
    float4 v = reinterpret_cast<const float4*>(x)[i];
    reinterpret_cast<__half2*>(h)[2*i]   = __half2(__float2half_rn(v.x), __float2half_rn(v.y));
    reinterpret_cast<__half2*>(h)[2*i+1] = __half2(__float2half_rn(v.z), __float2half_rn(v.w));
}

// ---------------- softmax: fp32 scores -> fp16 hi/lo probs ----------------
__global__ __launch_bounds__(256)
void softmax_kernel(const float* __restrict__ S, __half* __restrict__ Phi,
                    __half* __restrict__ Plo)
{
    __shared__ float red[8];
    const float* p = S + (size_t)blockIdx.x * SEQ;
    const int tid = threadIdx.x;

    float v[8];
    float mx = -1e30f;
    #pragma unroll
    for (int i = 0; i < 8; i++) { v[i] = p[tid + i * 256]; mx = fmaxf(mx, v[i]); }
    #pragma unroll
    for (int o = 16; o; o >>= 1) mx = fmaxf(mx, __shfl_xor_sync(0xffffffffu, mx, o));
    if ((tid & 31) == 0) red[tid >> 5] = mx;
    __syncthreads();
    mx = fmaxf(fmaxf(fmaxf(red[0], red[1]), fmaxf(red[2], red[3])),
               fmaxf(fmaxf(red[4], red[5]), fmaxf(red[6], red[7])));

    float sum = 0.f;
    #pragma unroll
    for (int i = 0; i < 8; i++) { v[i] = expf(v[i] - mx); sum += v[i]; }
    #pragma unroll
    for (int o = 16; o; o >>= 1) sum += __shfl_xor_sync(0xffffffffu, sum, o);
    __syncthreads();
    if ((tid & 31) == 0) red[tid >> 5] = sum;
    __syncthreads();
    sum = red[0] + red[1] + red[2] + red[3] + red[4] + red[5] + red[6] + red[7];

    float inv = 1.f / sum;
    __half* ph = Phi + (size_t)blockIdx.x * SEQ;
    __half* pl = Plo + (size_t)blockIdx.x * SEQ;
    #pragma unroll
    for (int i = 0; i < 8; i++) {
        float w = v[i] * inv;
        __half h = __float2half_rn(w);
        __half l = __float2half_rn(w - __half2float(h));
        ph[tid + i * 256] = h;
        pl[tid + i * 256] = l;
    }
}

// ---------------------------------------------------------------------------
extern "C" void kernel_launch(void* const* d_in, const int* in_sizes, int n_in,
                              void* d_out, int out_size)
{
    const float* X = (const float*)d_in[0];
    const float* W = (const float*)d_in[1];
    const float* b = (const float*)d_in[2];
    float* out = (float*)d_out;

    static bool attr_set = false;
    if (!attr_set) {
        cudaFuncSetAttribute(hmma_gemm<0,1>, cudaFuncAttributeMaxDynamicSharedMemorySize, NSTAGE * 2 * TILE_B);
        cudaFuncSetAttribute(hmma_gemm<1,2>, cudaFuncAttributeMaxDynamicSharedMemorySize, NSTAGE * 3 * TILE_B);
        cudaFuncSetAttribute(hmma_gemm<2,2>, cudaFuncAttributeMaxDynamicSharedMemorySize, NSTAGE * 3 * TILE_B);
        attr_set = true;
    }

    void *xh, *wh, *qhi, *qlo, *kh, *vTh, *sc, *phi, *plo;
    cudaGetSymbolAddress(&xh, g_xh);
    cudaGetSymbolAddress(&wh, g_wh);
    cudaGetSymbolAddress(&qhi, g_qhi); cudaGetSymbolAddress(&qlo, g_qlo);
    cudaGetSymbolAddress(&kh, g_kh);   cudaGetSymbolAddress(&vTh, g_vTh);
    cudaGetSymbolAddress(&sc, g_scores);
    cudaGetSymbolAddress(&phi, g_phi); cudaGetSymbolAddress(&plo, g_plo);

    // 1) truncate inputs to fp16
    cvt_f32<<<(TOK * HID / 4 + 255) / 256, 256>>>(X, (__half*)xh, TOK * HID / 4);
    cvt_f32<<<(NQKV * HID / 4 + 255) / 256, 256>>>(W, (__half*)wh, NQKV * HID / 4);

    // 2) QKV = X @ W^T + b  (M=8192, N=2304, K=768), 1-term
    hmma_gemm<0,1><<<dim3(NQKV / 128, TOK / 128, 1), 256, NSTAGE * 2 * TILE_B>>>(
        (__half*)xh, nullptr, (__half*)wh,
        HID, HID, HID, 0LL, 0LL, b, 1.0f, nullptr, 0LL, 0LL);

    // 3) scores = (Q @ K^T) / sqrt(768)  per batch (M=N=2048, K=768), 2-term
    hmma_gemm<1,2><<<dim3(SEQ / 128, SEQ / 128, BATCH), 256, NSTAGE * 3 * TILE_B>>>(
        (__half*)qhi, (__half*)qlo, (__half*)kh,
        HID, HID, HID, (long long)SEQ * HID, (long long)SEQ * HID,
        nullptr, rsqrtf((float)HID), (float*)sc, SEQ, (long long)SEQ * SEQ);

    // 4) softmax -> fp16 hi/lo probs
    softmax_kernel<<<BATCH * SEQ, 256>>>((const float*)sc, (__half*)phi, (__half*)plo);

    // 5) out = P @ V  per batch (M=2048, N=768, K=2048); B = vT (NT layout), 2-term
    hmma_gemm<2,2><<<dim3(HID / 128, SEQ / 128, BATCH), 256, NSTAGE * 3 * TILE_B>>>(
        (__half*)phi, (__half*)plo, (__half*)vTh,
        SEQ, SEQ, SEQ, (long long)SEQ * SEQ, (long long)HID * SEQ,
        nullptr, 1.0f, out, HID, (long long)SEQ * HID);
}

// round 8
// speedup vs baseline: 3.0706x; 1.3122x over previous
#include <cuda_runtime.h>
#include <cuda_fp16.h>
#include <cstdint>
#include <math.h>

#define BATCH 4
#define SEQ   2048
#define HID   768
#define NQKV  (3*HID)
#define TOK   (BATCH*SEQ)   // 8192

// ---------------- scratch (device globals; allocation-free) ----------------
__device__ __align__(128) __half g_xh [(size_t)TOK*HID];
__device__ __align__(128) __half g_wh [(size_t)NQKV*HID];
__device__ __align__(128) __half g_qh [(size_t)TOK*HID];
__device__ __align__(128) __half g_kh [(size_t)TOK*HID];
__device__ __align__(128) __half g_vTh[(size_t)BATCH*HID*SEQ];
__device__ __align__(128) float  g_scores[(size_t)BATCH*SEQ*SEQ];
__device__ __align__(128) __half g_ph [(size_t)BATCH*SEQ*SEQ];

// ---------------- PTX helpers (sm_80-compatible only) ----------------
__device__ __forceinline__ uint32_t smem_u32(const void* p) {
    uint32_t a;
    asm("{ .reg .u64 t; cvta.to.shared.u64 t, %1; cvt.u32.u64 %0, t; }" : "=r"(a) : "l"(p));
    return a;
}
__device__ __forceinline__ void cp16(uint32_t dst, const void* src) {
    asm volatile("cp.async.cg.shared.global [%0], [%1], 16;" :: "r"(dst), "l"(src));
}
#define CP_COMMIT() asm volatile("cp.async.commit_group;" ::: "memory")
#define CP_WAIT1()  asm volatile("cp.async.wait_group 1;" ::: "memory")

__device__ __forceinline__ void ldm4(uint32_t* r, uint32_t addr) {
    asm volatile("ldmatrix.sync.aligned.m8n8.x4.shared.b16 {%0,%1,%2,%3}, [%4];"
                 : "=r"(r[0]), "=r"(r[1]), "=r"(r[2]), "=r"(r[3]) : "r"(addr));
}
__device__ __forceinline__ void mma16816(float* c, const uint32_t* a, const uint32_t* b) {
    asm volatile("mma.sync.aligned.m16n8k16.row.col.f32.f16.f16.f32 "
                 "{%0,%1,%2,%3}, {%4,%5,%6,%7}, {%8,%9}, {%0,%1,%2,%3};"
                 : "+f"(c[0]), "+f"(c[1]), "+f"(c[2]), "+f"(c[3])
                 : "r"(a[0]), "r"(a[1]), "r"(a[2]), "r"(a[3]), "r"(b[0]), "r"(b[1]));
}

// -------- HMMA GEMM: C[128x128] = A(MxK) · B(NxK)^T, pure fp16 --------------
// SMEM tile: 128 rows x 32 fp16 padded to 80B/row. 2 tiles/stage, 3 stages.
#define ROWB    80
#define TILE_B  (128*ROWB)          // 10240
#define STAGE_B (2*TILE_B)          // 20480
#define NSTAGE  3
#define SM_TOTAL (NSTAGE*STAGE_B)   // 61440

// EPI: 0 = QKV (bias; Q,K fp16, V fp16 transposed), 1/2 = f32 out * alpha
template<int EPI>
__global__ __launch_bounds__(256, 1)
void hmma_gemm(const __half* __restrict__ Ah, const __half* __restrict__ Bh,
               long long lda, long long ldb, int K,
               long long sA, long long sB,
               const float* __restrict__ bias, float alpha,
               float* __restrict__ Cf, long long ldc, long long sC)
{
    extern __shared__ char smem[];
    const uint32_t sbase = smem_u32(smem);
    const int tid = threadIdx.x;
    const int bx = blockIdx.x, by = blockIdx.y, bz = blockIdx.z;
    const int wid = tid >> 5, lane = tid & 31;
    const int wm = wid & 1;          // 2 warps in M (64 rows each)
    const int wn = wid >> 1;         // 4 warps in N (32 cols each)

    const __half* a_h = Ah + bz * sA + (long long)by * 128 * lda;
    const __half* b_h = Bh + bz * sB + (long long)bx * 128 * ldb;

    // per-thread ldmatrix lane addressing
    const int m_in = (lane & 7) + 8 * ((lane >> 3) & 1);
    const int kb_a = (lane >> 4) * 16;
    const int n_in = (lane & 7) + 8 * (lane >> 4);
    const int kb_b = ((lane >> 3) & 1) * 16;
    const uint32_t a_row_off = (uint32_t)((wm * 64 + m_in) * ROWB + kb_a);
    const uint32_t b_row_off = (uint32_t)((wn * 32 + n_in) * ROWB + kb_b);

    float acc[4][4][4];
    #pragma unroll
    for (int i = 0; i < 4; i++)
        #pragma unroll
        for (int j = 0; j < 4; j++)
            #pragma unroll
            for (int r = 0; r < 4; r++) acc[i][j][r] = 0.f;

    const int nch = K / 32;

    auto load_stage = [&](int c, int slot) {
        const uint32_t dbase = sbase + (uint32_t)slot * STAGE_B;
        const long long k0 = (long long)c * 32;
        #pragma unroll
        for (int t = 0; t < 2; t++) {
            const __half* src = (t == 0) ? a_h : b_h;
            const long long ld = (t == 0) ? lda : ldb;
            #pragma unroll
            for (int p = 0; p < 2; p++) {
                int idx = tid + p * 256;        // 0..511
                int r = idx >> 2, ch = idx & 3;
                cp16(dbase + (uint32_t)(t * TILE_B + r * ROWB + ch * 16),
                     src + (long long)r * ld + k0 + ch * 8);
            }
        }
    };

    load_stage(0, 0); CP_COMMIT();
    load_stage(1, 1); CP_COMMIT();

    for (int c = 0; c < nch; c++) {
        CP_WAIT1();
        __syncthreads();
        if (c + 2 < nch) load_stage(c + 2, (c + 2) % NSTAGE);
        CP_COMMIT();

        const uint32_t st = sbase + (uint32_t)(c % NSTAGE) * STAGE_B;
        #pragma unroll
        for (int ks = 0; ks < 2; ks++) {
            uint32_t ah[4][4], bh[2][4];
            #pragma unroll
            for (int mi = 0; mi < 4; mi++) {
                uint32_t ao = st + a_row_off + (uint32_t)(mi * 16 * ROWB + ks * 32);
                ldm4(ah[mi], ao);
            }
            #pragma unroll
            for (int nj = 0; nj < 2; nj++) {
                uint32_t bo = st + TILE_B + b_row_off + (uint32_t)(nj * 16 * ROWB + ks * 32);
                ldm4(bh[nj], bo);
            }
            #pragma unroll
            for (int mi = 0; mi < 4; mi++)
                #pragma unroll
                for (int ni = 0; ni < 4; ni++)
                    mma16816(acc[mi][ni], ah[mi], &bh[ni >> 1][(ni & 1) * 2]);
        }
    }

    // ---------------- epilogue ----------------
    const int g = lane >> 2, t4 = lane & 3;
    const int row0 = by * 128 + wm * 64 + g;
    const int col0 = bx * 128 + wn * 32 + t4 * 2;

    if (EPI == 0) {
        const int seg = (bx * 128) / HID;          // 0=Q, 1=K, 2=V (tile never straddles)
        #pragma unroll
        for (int mi = 0; mi < 4; mi++)
            #pragma unroll
            for (int ni = 0; ni < 4; ni++)
                #pragma unroll
                for (int h = 0; h < 2; h++) {      // row halves (regs {0,1} vs {2,3})
                    long long row = row0 + mi * 16 + h * 8;
                    int col = col0 + ni * 8;
                    float v0 = acc[mi][ni][h * 2 + 0] + bias[col];
                    float v1 = acc[mi][ni][h * 2 + 1] + bias[col + 1];
                    __half h0 = __float2half_rn(v0);
                    __half h1 = __float2half_rn(v1);
                    if (seg == 0) {
                        *reinterpret_cast<__half2*>(g_qh + row * HID + col) = __half2(h0, h1);
                    } else if (seg == 1) {
                        *reinterpret_cast<__half2*>(g_kh + row * HID + (col - HID)) = __half2(h0, h1);
                    } else {
                        int hh = col - 2 * HID;
                        int b = (int)(row >> 11), s = (int)(row & 2047);
                        size_t o0 = ((size_t)b * HID + hh) * SEQ + s;
                        g_vTh[o0] = h0;
                        g_vTh[o0 + SEQ] = h1;
                    }
                }
    } else {
        float* cb = Cf + bz * sC;
        #pragma unroll
        for (int mi = 0; mi < 4; mi++)
            #pragma unroll
            for (int ni = 0; ni < 4; ni++)
                #pragma unroll
                for (int h = 0; h < 2; h++) {
                    long long row = row0 + mi * 16 + h * 8;
                    int col = col0 + ni * 8;
                    float2 o;
                    o.x = alpha * acc[mi][ni][h * 2 + 0];
                    o.y = alpha * acc[mi][ni][h * 2 + 1];
                    *reinterpret_cast<float2*>(cb + row * ldc + col) = o;
                }
    }
}

// ---------------- fp32 -> fp16 convert ----------------
__global__ __launch_bounds__(256)
void cvt_f32(const float* __restrict__ x, __half* __restrict__ h, int n4)
{
    int i = blockIdx.x * 256 + threadIdx.x;
    if (i >= n4) return;
    float4 v = reinterpret_cast<const float4*>(x)[i];
    reinterpret_cast<__half2*>(h)[2*i]   = __half2(__float2half_rn(v.x), __float2half_rn(v.y));
    reinterpret_cast<__half2*>(h)[2*i+1] = __half2(__float2half_rn(v.z), __float2half_rn(v.w));
}

// ---------------- softmax: fp32 scores -> fp16 probs ----------------
__global__ __launch_bounds__(256)
void softmax_kernel(const float* __restrict__ S, __half* __restrict__ P)
{
    __shared__ float red[8];
    const float* p = S + (size_t)blockIdx.x * SEQ;
    const int tid = threadIdx.x;

    float v[8];
    float mx = -1e30f;
    #pragma unroll
    for (int i = 0; i < 8; i++) { v[i] = p[tid + i * 256]; mx = fmaxf(mx, v[i]); }
    #pragma unroll
    for (int o = 16; o; o >>= 1) mx = fmaxf(mx, __shfl_xor_sync(0xffffffffu, mx, o));
    if ((tid & 31) == 0) red[tid >> 5] = mx;
    __syncthreads();
    mx = fmaxf(fmaxf(fmaxf(red[0], red[1]), fmaxf(red[2], red[3])),
               fmaxf(fmaxf(red[4], red[5]), fmaxf(red[6], red[7])));

    float sum = 0.f;
    #pragma unroll
    for (int i = 0; i < 8; i++) { v[i] = expf(v[i] - mx); sum += v[i]; }
    #pragma unroll
    for (int o = 16; o; o >>= 1) sum += __shfl_xor_sync(0xffffffffu, sum, o);
    __syncthreads();
    if ((tid & 31) == 0) red[tid >> 5] = sum;
    __syncthreads();
    sum = red[0] + red[1] + red[2] + red[3] + red[4] + red[5] + red[6] + red[7];

    float inv = 1.f / sum;
    __half* ph = P + (size_t)blockIdx.x * SEQ;
    #pragma unroll
    for (int i = 0; i < 4; i++) {
        __half2 o(__float2half_rn(v[2*i] * inv), __float2half_rn(v[2*i+1] * inv));
        // v[j] holds element tid + j*256; pack pairs from same thread's strided slots
        ph[tid + (2*i) * 256]   = o.x;
        ph[tid + (2*i+1) * 256] = o.y;
    }
}

// ---------------------------------------------------------------------------
extern "C" void kernel_launch(void* const* d_in, const int* in_sizes, int n_in,
                              void* d_out, int out_size)
{
    const float* X = (const float*)d_in[0];
    const float* W = (const float*)d_in[1];
    const float* b = (const float*)d_in[2];
    float* out = (float*)d_out;

    static bool attr_set = false;
    if (!attr_set) {
        cudaFuncSetAttribute(hmma_gemm<0>, cudaFuncAttributeMaxDynamicSharedMemorySize, SM_TOTAL);
        cudaFuncSetAttribute(hmma_gemm<1>, cudaFuncAttributeMaxDynamicSharedMemorySize, SM_TOTAL);
        cudaFuncSetAttribute(hmma_gemm<2>, cudaFuncAttributeMaxDynamicSharedMemorySize, SM_TOTAL);
        attr_set = true;
    }

    void *xh, *wh, *qh, *kh, *vTh, *sc, *ph;
    cudaGetSymbolAddress(&xh, g_xh);
    cudaGetSymbolAddress(&wh, g_wh);
    cudaGetSymbolAddress(&qh, g_qh);
    cudaGetSymbolAddress(&kh, g_kh);
    cudaGetSymbolAddress(&vTh, g_vTh);
    cudaGetSymbolAddress(&sc, g_scores);
    cudaGetSymbolAddress(&ph, g_ph);

    // 1) convert inputs to fp16
    cvt_f32<<<(TOK * HID / 4 + 255) / 256, 256>>>(X, (__half*)xh, TOK * HID / 4);
    cvt_f32<<<(NQKV * HID / 4 + 255) / 256, 256>>>(W, (__half*)wh, NQKV * HID / 4);

    // 2) QKV = X @ W^T + b  (M=8192, N=2304, K=768)
    hmma_gemm<0><<<dim3(NQKV / 128, TOK / 128, 1), 256, SM_TOTAL>>>(
        (__half*)xh, (__half*)wh,
        HID, HID, HID, 0LL, 0LL, b, 1.0f, nullptr, 0LL, 0LL);

    // 3) scores = (Q @ K^T) / sqrt(768)  per batch (M=N=2048, K=768)
    hmma_gemm<1><<<dim3(SEQ / 128, SEQ / 128, BATCH), 256, SM_TOTAL>>>(
        (__half*)qh, (__half*)kh,
        HID, HID, HID, (long long)SEQ * HID, (long long)SEQ * HID,
        nullptr, rsqrtf((float)HID), (float*)sc, SEQ, (long long)SEQ * SEQ);

    // 4) softmax -> fp16 probs
    softmax_kernel<<<BATCH * SEQ, 256>>>((const float*)sc, (__half*)ph);

    // 5) out = P @ V  per batch (M=2048, N=768, K=2048); B = vT (NT layout)
    hmma_gemm<2><<<dim3(HID / 128, SEQ / 128, BATCH), 256, SM_TOTAL>>>(
        (__half*)ph, (__half*)vTh,
        SEQ, SEQ, SEQ, (long long)SEQ * SEQ, (long long)HID * SEQ,
        nullptr, 1.0f, out, HID, (long long)SEQ * HID);
}

// round 10
// speedup vs baseline: 3.9114x; 1.2738x over previous
#include <cuda_runtime.h>
#include <cuda_fp16.h>
#include <cstdint>
#include <math.h>

#define BATCH 4
#define SEQ   2048
#define HID   768
#define NQKV  (3*HID)
#define TOK   (BATCH*SEQ)   // 8192

// ---------------- scratch (device globals; allocation-free) ----------------
__device__ __align__(128) __half g_xh [(size_t)TOK*HID];
__device__ __align__(128) __half g_wh [(size_t)NQKV*HID];
__device__ __align__(128) __half g_qh [(size_t)TOK*HID];
__device__ __align__(128) __half g_kh [(size_t)TOK*HID];
__device__ __align__(128) __half g_vTh[(size_t)BATCH*HID*SEQ];
__device__ __align__(128) float  g_scores[(size_t)BATCH*SEQ*SEQ];
__device__ __align__(128) __half g_ph [(size_t)BATCH*SEQ*SEQ];

// ---------------- PTX helpers (sm_80-compatible only) ----------------
__device__ __forceinline__ uint32_t smem_u32(const void* p) {
    uint32_t a;
    asm("{ .reg .u64 t; cvta.to.shared.u64 t, %1; cvt.u32.u64 %0, t; }" : "=r"(a) : "l"(p));
    return a;
}
__device__ __forceinline__ void cp16(uint32_t dst, const void* src) {
    asm volatile("cp.async.cg.shared.global [%0], [%1], 16;" :: "r"(dst), "l"(src));
}
#define CP_COMMIT() asm volatile("cp.async.commit_group;" ::: "memory")
#define CP_WAIT1()  asm volatile("cp.async.wait_group 1;" ::: "memory")

__device__ __forceinline__ void ldm4(uint32_t* r, uint32_t addr) {
    asm volatile("ldmatrix.sync.aligned.m8n8.x4.shared.b16 {%0,%1,%2,%3}, [%4];"
                 : "=r"(r[0]), "=r"(r[1]), "=r"(r[2]), "=r"(r[3]) : "r"(addr));
}
__device__ __forceinline__ void mma16816(float* c, const uint32_t* a, const uint32_t* b) {
    asm volatile("mma.sync.aligned.m16n8k16.row.col.f32.f16.f16.f32 "
                 "{%0,%1,%2,%3}, {%4,%5,%6,%7}, {%8,%9}, {%0,%1,%2,%3};"
                 : "+f"(c[0]), "+f"(c[1]), "+f"(c[2]), "+f"(c[3])
                 : "r"(a[0]), "r"(a[1]), "r"(a[2]), "r"(a[3]), "r"(b[0]), "r"(b[1]));
}

// -------- HMMA GEMM: C[128x128] = A(MxK) · B(NxK)^T, pure fp16 --------------
// SMEM tile: 128 rows x 32 fp16 padded to 80B/row. 2 tiles/stage, 3 stages.
// __launch_bounds__(256, 2): 2 CTAs/SM -> 4 warps/SMSP so ldmatrix/sync phases
// of one CTA overlap the MMA phase of the other (tensor pipe stays fed).
#define ROWB    80
#define TILE_B  (128*ROWB)          // 10240
#define STAGE_B (2*TILE_B)          // 20480
#define NSTAGE  3
#define SM_TOTAL (NSTAGE*STAGE_B)   // 61440 (x2 CTAs = 122880 < 228KB)

// EPI: 0 = QKV (bias; Q,K fp16, V fp16 transposed), 1/2 = f32 out * alpha
template<int EPI>
__global__ __launch_bounds__(256, 2)
void hmma_gemm(const __half* __restrict__ Ah, const __half* __restrict__ Bh,
               long long lda, long long ldb, int K,
               long long sA, long long sB,
               const float* __restrict__ bias, float alpha,
               float* __restrict__ Cf, long long ldc, long long sC)
{
    extern __shared__ char smem[];
    const uint32_t sbase = smem_u32(smem);
    const int tid = threadIdx.x;
    const int bx = blockIdx.x, by = blockIdx.y, bz = blockIdx.z;
    const int wid = tid >> 5, lane = tid & 31;
    const int wm = wid & 1;          // 2 warps in M (64 rows each)
    const int wn = wid >> 1;         // 4 warps in N (32 cols each)

    const __half* a_h = Ah + bz * sA + (long long)by * 128 * lda;
    const __half* b_h = Bh + bz * sB + (long long)bx * 128 * ldb;

    // per-thread ldmatrix lane addressing
    const int m_in = (lane & 7) + 8 * ((lane >> 3) & 1);
    const int kb_a = (lane >> 4) * 16;
    const int n_in = (lane & 7) + 8 * (lane >> 4);
    const int kb_b = ((lane >> 3) & 1) * 16;
    const uint32_t a_row_off = (uint32_t)((wm * 64 + m_in) * ROWB + kb_a);
    const uint32_t b_row_off = (uint32_t)((wn * 32 + n_in) * ROWB + kb_b);

    float acc[4][4][4];
    #pragma unroll
    for (int i = 0; i < 4; i++)
        #pragma unroll
        for (int j = 0; j < 4; j++)
            #pragma unroll
            for (int r = 0; r < 4; r++) acc[i][j][r] = 0.f;

    const int nch = K / 32;

    auto load_stage = [&](int c, int slot) {
        const uint32_t dbase = sbase + (uint32_t)slot * STAGE_B;
        const long long k0 = (long long)c * 32;
        #pragma unroll
        for (int t = 0; t < 2; t++) {
            const __half* src = (t == 0) ? a_h : b_h;
            const long long ld = (t == 0) ? lda : ldb;
            #pragma unroll
            for (int p = 0; p < 2; p++) {
                int idx = tid + p * 256;        // 0..511
                int r = idx >> 2, ch = idx & 3;
                cp16(dbase + (uint32_t)(t * TILE_B + r * ROWB + ch * 16),
                     src + (long long)r * ld + k0 + ch * 8);
            }
        }
    };

    load_stage(0, 0); CP_COMMIT();
    load_stage(1, 1); CP_COMMIT();

    for (int c = 0; c < nch; c++) {
        CP_WAIT1();
        __syncthreads();
        if (c + 2 < nch) load_stage(c + 2, (c + 2) % NSTAGE);
        CP_COMMIT();

        const uint32_t st = sbase + (uint32_t)(c % NSTAGE) * STAGE_B;
        #pragma unroll
        for (int ks = 0; ks < 2; ks++) {
            uint32_t ah[4][4], bh[2][4];
            #pragma unroll
            for (int mi = 0; mi < 4; mi++) {
                uint32_t ao = st + a_row_off + (uint32_t)(mi * 16 * ROWB + ks * 32);
                ldm4(ah[mi], ao);
            }
            #pragma unroll
            for (int nj = 0; nj < 2; nj++) {
                uint32_t bo = st + TILE_B + b_row_off + (uint32_t)(nj * 16 * ROWB + ks * 32);
                ldm4(bh[nj], bo);
            }
            #pragma unroll
            for (int mi = 0; mi < 4; mi++)
                #pragma unroll
                for (int ni = 0; ni < 4; ni++)
                    mma16816(acc[mi][ni], ah[mi], &bh[ni >> 1][(ni & 1) * 2]);
        }
    }

    // ---------------- epilogue ----------------
    const int g = lane >> 2, t4 = lane & 3;
    const int row0 = by * 128 + wm * 64 + g;
    const int col0 = bx * 128 + wn * 32 + t4 * 2;

    if (EPI == 0) {
        const int seg = (bx * 128) / HID;          // 0=Q, 1=K, 2=V (tile never straddles)
        #pragma unroll
        for (int mi = 0; mi < 4; mi++)
            #pragma unroll
            for (int ni = 0; ni < 4; ni++)
                #pragma unroll
                for (int h = 0; h < 2; h++) {      // row halves (regs {0,1} vs {2,3})
                    long long row = row0 + mi * 16 + h * 8;
                    int col = col0 + ni * 8;
                    float v0 = acc[mi][ni][h * 2 + 0] + bias[col];
                    float v1 = acc[mi][ni][h * 2 + 1] + bias[col + 1];
                    __half h0 = __float2half_rn(v0);
                    __half h1 = __float2half_rn(v1);
                    if (seg == 0) {
                        *reinterpret_cast<__half2*>(g_qh + row * HID + col) = __half2(h0, h1);
                    } else if (seg == 1) {
                        *reinterpret_cast<__half2*>(g_kh + row * HID + (col - HID)) = __half2(h0, h1);
                    } else {
                        int hh = col - 2 * HID;
                        int b = (int)(row >> 11), s = (int)(row & 2047);
                        size_t o0 = ((size_t)b * HID + hh) * SEQ + s;
                        g_vTh[o0] = h0;
                        g_vTh[o0 + SEQ] = h1;
                    }
                }
    } else {
        float* cb = Cf + bz * sC;
        #pragma unroll
        for (int mi = 0; mi < 4; mi++)
            #pragma unroll
            for (int ni = 0; ni < 4; ni++)
                #pragma unroll
                for (int h = 0; h < 2; h++) {
                    long long row = row0 + mi * 16 + h * 8;
                    int col = col0 + ni * 8;
                    float2 o;
                    o.x = alpha * acc[mi][ni][h * 2 + 0];
                    o.y = alpha * acc[mi][ni][h * 2 + 1];
                    *reinterpret_cast<float2*>(cb + row * ldc + col) = o;
                }
    }
}

// ---------------- fp32 -> fp16 convert ----------------
__global__ __launch_bounds__(256)
void cvt_f32(const float* __restrict__ x, __half* __restrict__ h, int n4)
{
    int i = blockIdx.x * 256 + threadIdx.x;
    if (i >= n4) return;
    float4 v = reinterpret_cast<const float4*>(x)[i];
    reinterpret_cast<__half2*>(h)[2*i]   = __half2(__float2half_rn(v.x), __float2half_rn(v.y));
    reinterpret_cast<__half2*>(h)[2*i+1] = __half2(__float2half_rn(v.z), __float2half_rn(v.w));
}

// ---------------- softmax: fp32 scores -> fp16 probs ----------------
__global__ __launch_bounds__(256)
void softmax_kernel(const float* __restrict__ S, __half* __restrict__ P)
{
    __shared__ float red[8];
    const float* p = S + (size_t)blockIdx.x * SEQ;
    const int tid = threadIdx.x;

    float v[8];
    float mx = -1e30f;
    #pragma unroll
    for (int i = 0; i < 8; i++) { v[i] = p[tid + i * 256]; mx = fmaxf(mx, v[i]); }
    #pragma unroll
    for (int o = 16; o; o >>= 1) mx = fmaxf(mx, __shfl_xor_sync(0xffffffffu, mx, o));
    if ((tid & 31) == 0) red[tid >> 5] = mx;
    __syncthreads();
    mx = fmaxf(fmaxf(fmaxf(red[0], red[1]), fmaxf(red[2], red[3])),
               fmaxf(fmaxf(red[4], red[5]), fmaxf(red[6], red[7])));

    float sum = 0.f;
    #pragma unroll
    for (int i = 0; i < 8; i++) { v[i] = expf(v[i] - mx); sum += v[i]; }
    #pragma unroll
    for (int o = 16; o; o >>= 1) sum += __shfl_xor_sync(0xffffffffu, sum, o);
    __syncthreads();
    if ((tid & 31) == 0) red[tid >> 5] = sum;
    __syncthreads();
    sum = red[0] + red[1] + red[2] + red[3] + red[4] + red[5] + red[6] + red[7];

    float inv = 1.f / sum;
    __half* ph = P + (size_t)blockIdx.x * SEQ;
    #pragma unroll
    for (int i = 0; i < 8; i++)
        ph[tid + i * 256] = __float2half_rn(v[i] * inv);
}

// ---------------------------------------------------------------------------
extern "C" void kernel_launch(void* const* d_in, const int* in_sizes, int n_in,
                              void* d_out, int out_size)
{
    const float* X = (const float*)d_in[0];
    const float* W = (const float*)d_in[1];
    const float* b = (const float*)d_in[2];
    float* out = (float*)d_out;

    static bool attr_set = false;
    if (!attr_set) {
        cudaFuncSetAttribute(hmma_gemm<0>, cudaFuncAttributeMaxDynamicSharedMemorySize, SM_TOTAL);
        cudaFuncSetAttribute(hmma_gemm<1>, cudaFuncAttributeMaxDynamicSharedMemorySize, SM_TOTAL);
        cudaFuncSetAttribute(hmma_gemm<2>, cudaFuncAttributeMaxDynamicSharedMemorySize, SM_TOTAL);
        attr_set = true;
    }

    void *xh, *wh, *qh, *kh, *vTh, *sc, *ph;
    cudaGetSymbolAddress(&xh, g_xh);
    cudaGetSymbolAddress(&wh, g_wh);
    cudaGetSymbolAddress(&qh, g_qh);
    cudaGetSymbolAddress(&kh, g_kh);
    cudaGetSymbolAddress(&vTh, g_vTh);
    cudaGetSymbolAddress(&sc, g_scores);
    cudaGetSymbolAddress(&ph, g_ph);

    // 1) convert inputs to fp16
    cvt_f32<<<(TOK * HID / 4 + 255) / 256, 256>>>(X, (__half*)xh, TOK * HID / 4);
    cvt_f32<<<(NQKV * HID / 4 + 255) / 256, 256>>>(W, (__half*)wh, NQKV * HID / 4);

    // 2) QKV = X @ W^T + b  (M=8192, N=2304, K=768)
    hmma_gemm<0><<<dim3(NQKV / 128, TOK / 128, 1), 256, SM_TOTAL>>>(
        (__half*)xh, (__half*)wh,
        HID, HID, HID, 0LL, 0LL, b, 1.0f, nullptr, 0LL, 0LL);

    // 3) scores = (Q @ K^T) / sqrt(768)  per batch (M=N=2048, K=768)
    hmma_gemm<1><<<dim3(SEQ / 128, SEQ / 128, BATCH), 256, SM_TOTAL>>>(
        (__half*)qh, (__half*)kh,
        HID, HID, HID, (long long)SEQ * HID, (long long)SEQ * HID,
        nullptr, rsqrtf((float)HID), (float*)sc, SEQ, (long long)SEQ * SEQ);

    // 4) softmax -> fp16 probs
    softmax_kernel<<<BATCH * SEQ, 256>>>((const float*)sc, (__half*)ph);

    // 5) out = P @ V  per batch (M=2048, N=768, K=2048); B = vT (NT layout)
    hmma_gemm<2><<<dim3(HID / 128, SEQ / 128, BATCH), 256, SM_TOTAL>>>(
        (__half*)ph, (__half*)vTh,
        SEQ, SEQ, SEQ, (long long)SEQ * SEQ, (long long)HID * SEQ,
        nullptr, 1.0f, out, HID, (long long)SEQ * HID);
}

// round 13
// speedup vs baseline: 4.7325x; 1.2099x over previous
#include <cuda_runtime.h>
#include <cuda_fp16.h>
#include <cstdint>
#include <math.h>

#define BATCH 4
#define SEQ   2048
#define HID   768
#define NQKV  (3*HID)
#define TOK   (BATCH*SEQ)   // 8192

// ---------------- scratch (device globals; allocation-free) ----------------
__device__ __align__(128) __half g_xh [(size_t)TOK*HID];
__device__ __align__(128) __half g_wh [(size_t)NQKV*HID];
__device__ __align__(128) __half g_qh [(size_t)TOK*HID];
__device__ __align__(128) __half g_kh [(size_t)TOK*HID];
__device__ __align__(128) __half g_vTh[(size_t)BATCH*HID*SEQ];
__device__ __align__(128) float  g_scores[(size_t)BATCH*SEQ*SEQ];
__device__ __align__(128) __half g_ph [(size_t)BATCH*SEQ*SEQ];

// ---------------- PTX helpers (sm_80-compatible only) ----------------
__device__ __forceinline__ uint32_t smem_u32(const void* p) {
    uint32_t a;
    asm("{ .reg .u64 t; cvta.to.shared.u64 t, %1; cvt.u32.u64 %0, t; }" : "=r"(a) : "l"(p));
    return a;
}
__device__ __forceinline__ void cp16(uint32_t dst, const void* src) {
    asm volatile("cp.async.cg.shared.global [%0], [%1], 16;" :: "r"(dst), "l"(src));
}
#define CP_COMMIT() asm volatile("cp.async.commit_group;" ::: "memory")
#define CP_WAIT1()  asm volatile("cp.async.wait_group 1;" ::: "memory")

__device__ __forceinline__ void ldm4(uint32_t* r, uint32_t addr) {
    asm volatile("ldmatrix.sync.aligned.m8n8.x4.shared.b16 {%0,%1,%2,%3}, [%4];"
                 : "=r"(r[0]), "=r"(r[1]), "=r"(r[2]), "=r"(r[3]) : "r"(addr));
}
__device__ __forceinline__ void mma16816(float* c, const uint32_t* a, const uint32_t* b) {
    asm volatile("mma.sync.aligned.m16n8k16.row.col.f32.f16.f16.f32 "
                 "{%0,%1,%2,%3}, {%4,%5,%6,%7}, {%8,%9}, {%0,%1,%2,%3};"
                 : "+f"(c[0]), "+f"(c[1]), "+f"(c[2]), "+f"(c[3])
                 : "r"(a[0]), "r"(a[1]), "r"(a[2]), "r"(a[3]), "r"(b[0]), "r"(b[1]));
}

// SW128-style swizzle for 128B rows: XOR row low-3 bits (off[9:7]) into the
// 16B-column bits (off[6:4]). Each 8-row ldmatrix phase then hits 8 distinct
// 16B columns -> conflict-free, no padding.
__device__ __forceinline__ uint32_t swz(uint32_t off) {
    return off ^ ((off >> 3) & 0x70u);
}

// -------- HMMA GEMM: C[128x128] = A(MxK) · B(NxK)^T, pure fp16 --------------
// K-chunk = 64: SMEM tile 128 rows x 64 fp16 = 128B rows, XOR-swizzled.
// 2 tiles/stage, 3 stages, 2 CTAs/SM. Per __syncthreads: 32 MMAs + 12 ldm4
// (was 16 + 6 at BK=32) -> amortizes sync/stage overhead.
#define ROWB    128
#define TILE_B  (128*ROWB)          // 16384
#define STAGE_B (2*TILE_B)          // 32768
#define NSTAGE  3
#define SM_TOTAL (NSTAGE*STAGE_B)   // 98304 (x2 CTAs = 196608, fits easily)

// EPI: 0 = QKV (bias; Q,K fp16, V fp16 transposed), 1/2 = f32 out * alpha
template<int EPI>
__global__ __launch_bounds__(256, 2)
void hmma_gemm(const __half* __restrict__ Ah, const __half* __restrict__ Bh,
               long long lda, long long ldb, int K,
               long long sA, long long sB,
               const float* __restrict__ bias, float alpha,
               float* __restrict__ Cf, long long ldc, long long sC)
{
    extern __shared__ char smem[];
    const uint32_t sbase = smem_u32(smem);
    const int tid = threadIdx.x;
    const int bx = blockIdx.x, by = blockIdx.y, bz = blockIdx.z;
    const int wid = tid >> 5, lane = tid & 31;
    const int wm = wid & 1;          // 2 warps in M (64 rows each)
    const int wn = wid >> 1;         // 4 warps in N (32 cols each)

    const __half* a_h = Ah + bz * sA + (long long)by * 128 * lda;
    const __half* b_h = Bh + bz * sB + (long long)bx * 128 * ldb;

    // per-thread ldmatrix lane addressing (pre-swizzle offsets)
    const int m_in = (lane & 7) + 8 * ((lane >> 3) & 1);
    const int kb_a = (lane >> 4) * 16;
    const int n_in = (lane & 7) + 8 * (lane >> 4);
    const int kb_b = ((lane >> 3) & 1) * 16;
    const uint32_t a_row_off = (uint32_t)((wm * 64 + m_in) * ROWB + kb_a);
    const uint32_t b_row_off = (uint32_t)((wn * 32 + n_in) * ROWB + kb_b);

    float acc[4][4][4];
    #pragma unroll
    for (int i = 0; i < 4; i++)
        #pragma unroll
        for (int j = 0; j < 4; j++)
            #pragma unroll
            for (int r = 0; r < 4; r++) acc[i][j][r] = 0.f;

    const int nch = K / 64;

    // stage loader: 2 tiles x 1024 16B-slots / 256 threads = 8 cp16/thread
    auto load_stage = [&](int c, int slot) {
        const uint32_t dbase = sbase + (uint32_t)slot * STAGE_B;
        const long long k0 = (long long)c * 64;
        #pragma unroll
        for (int t = 0; t < 2; t++) {
            const __half* src = (t == 0) ? a_h : b_h;
            const long long ld = (t == 0) ? lda : ldb;
            #pragma unroll
            for (int p = 0; p < 4; p++) {
                int idx = tid + p * 256;        // 0..1023
                int r = idx >> 3, ch = idx & 7;
                cp16(dbase + (uint32_t)t * TILE_B + swz((uint32_t)(r * ROWB + ch * 16)),
                     src + (long long)r * ld + k0 + ch * 8);
            }
        }
    };

    load_stage(0, 0); CP_COMMIT();
    load_stage(1, 1); CP_COMMIT();

    for (int c = 0; c < nch; c++) {
        CP_WAIT1();
        __syncthreads();
        if (c + 2 < nch) load_stage(c + 2, (c + 2) % NSTAGE);
        CP_COMMIT();

        const uint32_t st = sbase + (uint32_t)(c % NSTAGE) * STAGE_B;
        #pragma unroll
        for (int ks = 0; ks < 4; ks++) {
            uint32_t ah[4][4], bh[2][4];
            #pragma unroll
            for (int mi = 0; mi < 4; mi++) {
                uint32_t ao = a_row_off + (uint32_t)(mi * 16 * ROWB + ks * 32);
                ldm4(ah[mi], st + swz(ao));
            }
            #pragma unroll
            for (int nj = 0; nj < 2; nj++) {
                uint32_t bo = b_row_off + (uint32_t)(nj * 16 * ROWB + ks * 32);
                ldm4(bh[nj], st + TILE_B + swz(bo));
            }
            #pragma unroll
            for (int mi = 0; mi < 4; mi++)
                #pragma unroll
                for (int ni = 0; ni < 4; ni++)
                    mma16816(acc[mi][ni], ah[mi], &bh[ni >> 1][(ni & 1) * 2]);
        }
    }

    // ---------------- epilogue ----------------
    const int g = lane >> 2, t4 = lane & 3;
    const int row0 = by * 128 + wm * 64 + g;
    const int col0 = bx * 128 + wn * 32 + t4 * 2;

    if (EPI == 0) {
        const int seg = (bx * 128) / HID;          // 0=Q, 1=K, 2=V (tile never straddles)
        #pragma unroll
        for (int mi = 0; mi < 4; mi++)
            #pragma unroll
            for (int ni = 0; ni < 4; ni++)
                #pragma unroll
                for (int h = 0; h < 2; h++) {      // row halves (regs {0,1} vs {2,3})
                    long long row = row0 + mi * 16 + h * 8;
                    int col = col0 + ni * 8;
                    float v0 = acc[mi][ni][h * 2 + 0] + bias[col];
                    float v1 = acc[mi][ni][h * 2 + 1] + bias[col + 1];
                    __half h0 = __float2half_rn(v0);
                    __half h1 = __float2half_rn(v1);
                    if (seg == 0) {
                        *reinterpret_cast<__half2*>(g_qh + row * HID + col) = __half2(h0, h1);
                    } else if (seg == 1) {
                        *reinterpret_cast<__half2*>(g_kh + row * HID + (col - HID)) = __half2(h0, h1);
                    } else {
                        int hh = col - 2 * HID;
                        int b = (int)(row >> 11), s = (int)(row & 2047);
                        size_t o0 = ((size_t)b * HID + hh) * SEQ + s;
                        g_vTh[o0] = h0;
                        g_vTh[o0 + SEQ] = h1;
                    }
                }
    } else {
        float* cb = Cf + bz * sC;
        #pragma unroll
        for (int mi = 0; mi < 4; mi++)
            #pragma unroll
            for (int ni = 0; ni < 4; ni++)
                #pragma unroll
                for (int h = 0; h < 2; h++) {
                    long long row = row0 + mi * 16 + h * 8;
                    int col = col0 + ni * 8;
                    float2 o;
                    o.x = alpha * acc[mi][ni][h * 2 + 0];
                    o.y = alpha * acc[mi][ni][h * 2 + 1];
                    *reinterpret_cast<float2*>(cb + row * ldc + col) = o;
                }
    }
}

// ---------------- fp32 -> fp16 convert ----------------
__global__ __launch_bounds__(256)
void cvt_f32(const float* __restrict__ x, __half* __restrict__ h, int n4)
{
    int i = blockIdx.x * 256 + threadIdx.x;
    if (i >= n4) return;
    float4 v = reinterpret_cast<const float4*>(x)[i];
    reinterpret_cast<__half2*>(h)[2*i]   = __half2(__float2half_rn(v.x), __float2half_rn(v.y));
    reinterpret_cast<__half2*>(h)[2*i+1] = __half2(__float2half_rn(v.z), __float2half_rn(v.w));
}

// ---------------- softmax: fp32 scores -> fp16 probs ----------------
__global__ __launch_bounds__(256)
void softmax_kernel(const float* __restrict__ S, __half* __restrict__ P)
{
    __shared__ float red[8];
    const float* p = S + (size_t)blockIdx.x * SEQ;
    const int tid = threadIdx.x;

    float v[8];
    float mx = -1e30f;
    #pragma unroll
    for (int i = 0; i < 8; i++) { v[i] = p[tid + i * 256]; mx = fmaxf(mx, v[i]); }
    #pragma unroll
    for (int o = 16; o; o >>= 1) mx = fmaxf(mx, __shfl_xor_sync(0xffffffffu, mx, o));
    if ((tid & 31) == 0) red[tid >> 5] = mx;
    __syncthreads();
    mx = fmaxf(fmaxf(fmaxf(red[0], red[1]), fmaxf(red[2], red[3])),
               fmaxf(fmaxf(red[4], red[5]), fmaxf(red[6], red[7])));

    float sum = 0.f;
    #pragma unroll
    for (int i = 0; i < 8; i++) { v[i] = expf(v[i] - mx); sum += v[i]; }
    #pragma unroll
    for (int o = 16; o; o >>= 1) sum += __shfl_xor_sync(0xffffffffu, sum, o);
    __syncthreads();
    if ((tid & 31) == 0) red[tid >> 5] = sum;
    __syncthreads();
    sum = red[0] + red[1] + red[2] + red[3] + red[4] + red[5] + red[6] + red[7];

    float inv = 1.f / sum;
    __half* ph = P + (size_t)blockIdx.x * SEQ;
    #pragma unroll
    for (int i = 0; i < 8; i++)
        ph[tid + i * 256] = __float2half_rn(v[i] * inv);
}

// ---------------------------------------------------------------------------
extern "C" void kernel_launch(void* const* d_in, const int* in_sizes, int n_in,
                              void* d_out, int out_size)
{
    const float* X = (const float*)d_in[0];
    const float* W = (const float*)d_in[1];
    const float* b = (const float*)d_in[2];
    float* out = (float*)d_out;

    static bool attr_set = false;
    if (!attr_set) {
        cudaFuncSetAttribute(hmma_gemm<0>, cudaFuncAttributeMaxDynamicSharedMemorySize, SM_TOTAL);
        cudaFuncSetAttribute(hmma_gemm<1>, cudaFuncAttributeMaxDynamicSharedMemorySize, SM_TOTAL);
        cudaFuncSetAttribute(hmma_gemm<2>, cudaFuncAttributeMaxDynamicSharedMemorySize, SM_TOTAL);
        attr_set = true;
    }

    void *xh, *wh, *qh, *kh, *vTh, *sc, *ph;
    cudaGetSymbolAddress(&xh, g_xh);
    cudaGetSymbolAddress(&wh, g_wh);
    cudaGetSymbolAddress(&qh, g_qh);
    cudaGetSymbolAddress(&kh, g_kh);
    cudaGetSymbolAddress(&vTh, g_vTh);
    cudaGetSymbolAddress(&sc, g_scores);
    cudaGetSymbolAddress(&ph, g_ph);

    // 1) convert inputs to fp16
    cvt_f32<<<(TOK * HID / 4 + 255) / 256, 256>>>(X, (__half*)xh, TOK * HID / 4);
    cvt_f32<<<(NQKV * HID / 4 + 255) / 256, 256>>>(W, (__half*)wh, NQKV * HID / 4);

    // 2) QKV = X @ W^T + b  (M=8192, N=2304, K=768)
    hmma_gemm<0><<<dim3(NQKV / 128, TOK / 128, 1), 256, SM_TOTAL>>>(
        (__half*)xh, (__half*)wh,
        HID, HID, HID, 0LL, 0LL, b, 1.0f, nullptr, 0LL, 0LL);

    // 3) scores = (Q @ K^T) / sqrt(768)  per batch (M=N=2048, K=768)
    hmma_gemm<1><<<dim3(SEQ / 128, SEQ / 128, BATCH), 256, SM_TOTAL>>>(
        (__half*)qh, (__half*)kh,
        HID, HID, HID, (long long)SEQ * HID, (long long)SEQ * HID,
        nullptr, rsqrtf((float)HID), (float*)sc, SEQ, (long long)SEQ * SEQ);

    // 4) softmax -> fp16 probs
    softmax_kernel<<<BATCH * SEQ, 256>>>((const float*)sc, (__half*)ph);

    // 5) out = P @ V  per batch (M=2048, N=768, K=2048); B = vT (NT layout)
    hmma_gemm<2><<<dim3(HID / 128, SEQ / 128, BATCH), 256, SM_TOTAL>>>(
        (__half*)ph, (__half*)vTh,
        SEQ, SEQ, SEQ, (long long)SEQ * SEQ, (long long)HID * SEQ,
        nullptr, 1.0f, out, HID, (long long)SEQ * HID);
}

// round 14
// speedup vs baseline: 4.8692x; 1.0289x over previous
#include <cuda_runtime.h>
#include <cuda_fp16.h>
#include <cstdint>
#include <math.h>

#define BATCH 4
#define SEQ   2048
#define HID   768
#define NQKV  (3*HID)
#define TOK   (BATCH*SEQ)   // 8192

// ---------------- scratch (device globals; allocation-free) ----------------
__device__ __align__(128) __half g_xh [(size_t)TOK*HID];
__device__ __align__(128) __half g_wh [(size_t)NQKV*HID];
__device__ __align__(128) __half g_qh [(size_t)TOK*HID];
__device__ __align__(128) __half g_kh [(size_t)TOK*HID];
__device__ __align__(128) __half g_vTh[(size_t)BATCH*HID*SEQ];
__device__ __align__(128) __half g_ph [(size_t)BATCH*SEQ*SEQ];   // unnormalized exp(scores), fp16
__device__ __align__(128) float  g_inv[(size_t)BATCH*SEQ];       // per-row 1/rowsum

// ---------------- PTX helpers (sm_80-compatible only) ----------------
__device__ __forceinline__ uint32_t smem_u32(const void* p) {
    uint32_t a;
    asm("{ .reg .u64 t; cvta.to.shared.u64 t, %1; cvt.u32.u64 %0, t; }" : "=r"(a) : "l"(p));
    return a;
}
__device__ __forceinline__ void cp16(uint32_t dst, const void* src) {
    asm volatile("cp.async.cg.shared.global [%0], [%1], 16;" :: "r"(dst), "l"(src));
}
#define CP_COMMIT() asm volatile("cp.async.commit_group;" ::: "memory")
#define CP_WAIT1()  asm volatile("cp.async.wait_group 1;" ::: "memory")

__device__ __forceinline__ void ldm4(uint32_t* r, uint32_t addr) {
    asm volatile("ldmatrix.sync.aligned.m8n8.x4.shared.b16 {%0,%1,%2,%3}, [%4];"
                 : "=r"(r[0]), "=r"(r[1]), "=r"(r[2]), "=r"(r[3]) : "r"(addr));
}
__device__ __forceinline__ void mma16816(float* c, const uint32_t* a, const uint32_t* b) {
    asm volatile("mma.sync.aligned.m16n8k16.row.col.f32.f16.f16.f32 "
                 "{%0,%1,%2,%3}, {%4,%5,%6,%7}, {%8,%9}, {%0,%1,%2,%3};"
                 : "+f"(c[0]), "+f"(c[1]), "+f"(c[2]), "+f"(c[3])
                 : "r"(a[0]), "r"(a[1]), "r"(a[2]), "r"(a[3]), "r"(b[0]), "r"(b[1]));
}

// SW128-style swizzle for 128B rows: XOR off[9:7] into off[6:4].
__device__ __forceinline__ uint32_t swz(uint32_t off) {
    return off ^ ((off >> 3) & 0x70u);
}

// -------- HMMA GEMM: C[128x128] = A(MxK) · B(NxK)^T, pure fp16 --------------
// K-chunk = 64, swizzled 128B rows, 2 tiles/stage, 3 stages, 2 CTAs/SM.
#define ROWB    128
#define TILE_B  (128*ROWB)          // 16384
#define STAGE_B (2*TILE_B)          // 32768
#define NSTAGE  3
#define SM_TOTAL (NSTAGE*STAGE_B)   // 98304 (x2 CTAs = 196608)

// EPI: 0 = QKV (bias; Q,K fp16, V fp16 transposed)
//      1 = QK: P = exp(score) as fp16 (alpha = scale*log2e, exp2f)
//      2 = PV: f32 out scaled by per-row g_inv
template<int EPI>
__global__ __launch_bounds__(256, 2)
void hmma_gemm(const __half* __restrict__ Ah, const __half* __restrict__ Bh,
               long long lda, long long ldb, int K,
               long long sA, long long sB,
               const float* __restrict__ bias, float alpha,
               void* __restrict__ Cp, long long ldc, long long sC)
{
    extern __shared__ char smem[];
    const uint32_t sbase = smem_u32(smem);
    const int tid = threadIdx.x;
    const int bx = blockIdx.x, by = blockIdx.y, bz = blockIdx.z;
    const int wid = tid >> 5, lane = tid & 31;
    const int wm = wid & 1;          // 2 warps in M (64 rows each)
    const int wn = wid >> 1;         // 4 warps in N (32 cols each)

    const __half* a_h = Ah + bz * sA + (long long)by * 128 * lda;
    const __half* b_h = Bh + bz * sB + (long long)bx * 128 * ldb;

    // per-thread ldmatrix lane addressing (pre-swizzle offsets)
    const int m_in = (lane & 7) + 8 * ((lane >> 3) & 1);
    const int kb_a = (lane >> 4) * 16;
    const int n_in = (lane & 7) + 8 * (lane >> 4);
    const int kb_b = ((lane >> 3) & 1) * 16;
    const uint32_t a_row_off = (uint32_t)((wm * 64 + m_in) * ROWB + kb_a);
    const uint32_t b_row_off = (uint32_t)((wn * 32 + n_in) * ROWB + kb_b);

    float acc[4][4][4];
    #pragma unroll
    for (int i = 0; i < 4; i++)
        #pragma unroll
        for (int j = 0; j < 4; j++)
            #pragma unroll
            for (int r = 0; r < 4; r++) acc[i][j][r] = 0.f;

    const int nch = K / 64;

    auto load_stage = [&](int c, int slot) {
        const uint32_t dbase = sbase + (uint32_t)slot * STAGE_B;
        const long long k0 = (long long)c * 64;
        #pragma unroll
        for (int t = 0; t < 2; t++) {
            const __half* src = (t == 0) ? a_h : b_h;
            const long long ld = (t == 0) ? lda : ldb;
            #pragma unroll
            for (int p = 0; p < 4; p++) {
                int idx = tid + p * 256;        // 0..1023
                int r = idx >> 3, ch = idx & 7;
                cp16(dbase + (uint32_t)t * TILE_B + swz((uint32_t)(r * ROWB + ch * 16)),
                     src + (long long)r * ld + k0 + ch * 8);
            }
        }
    };

    load_stage(0, 0); CP_COMMIT();
    load_stage(1, 1); CP_COMMIT();

    for (int c = 0; c < nch; c++) {
        CP_WAIT1();
        __syncthreads();
        if (c + 2 < nch) load_stage(c + 2, (c + 2) % NSTAGE);
        CP_COMMIT();

        const uint32_t st = sbase + (uint32_t)(c % NSTAGE) * STAGE_B;
        #pragma unroll
        for (int ks = 0; ks < 4; ks++) {
            uint32_t ah[4][4], bh[2][4];
            #pragma unroll
            for (int mi = 0; mi < 4; mi++) {
                uint32_t ao = a_row_off + (uint32_t)(mi * 16 * ROWB + ks * 32);
                ldm4(ah[mi], st + swz(ao));
            }
            #pragma unroll
            for (int nj = 0; nj < 2; nj++) {
                uint32_t bo = b_row_off + (uint32_t)(nj * 16 * ROWB + ks * 32);
                ldm4(bh[nj], st + TILE_B + swz(bo));
            }
            #pragma unroll
            for (int mi = 0; mi < 4; mi++)
                #pragma unroll
                for (int ni = 0; ni < 4; ni++)
                    mma16816(acc[mi][ni], ah[mi], &bh[ni >> 1][(ni & 1) * 2]);
        }
    }

    // ---------------- epilogue ----------------
    const int g = lane >> 2, t4 = lane & 3;
    const int row0 = by * 128 + wm * 64 + g;
    const int col0 = bx * 128 + wn * 32 + t4 * 2;

    if (EPI == 0) {
        const float* bias_p = bias;
        const int seg = (bx * 128) / HID;          // 0=Q, 1=K, 2=V (tile never straddles)
        #pragma unroll
        for (int mi = 0; mi < 4; mi++)
            #pragma unroll
            for (int ni = 0; ni < 4; ni++)
                #pragma unroll
                for (int h = 0; h < 2; h++) {
                    long long row = row0 + mi * 16 + h * 8;
                    int col = col0 + ni * 8;
                    float v0 = acc[mi][ni][h * 2 + 0] + bias_p[col];
                    float v1 = acc[mi][ni][h * 2 + 1] + bias_p[col + 1];
                    __half h0 = __float2half_rn(v0);
                    __half h1 = __float2half_rn(v1);
                    if (seg == 0) {
                        *reinterpret_cast<__half2*>(g_qh + row * HID + col) = __half2(h0, h1);
                    } else if (seg == 1) {
                        *reinterpret_cast<__half2*>(g_kh + row * HID + (col - HID)) = __half2(h0, h1);
                    } else {
                        int hh = col - 2 * HID;
                        int b = (int)(row >> 11), s = (int)(row & 2047);
                        size_t o0 = ((size_t)b * HID + hh) * SEQ + s;
                        g_vTh[o0] = h0;
                        g_vTh[o0 + SEQ] = h1;
                    }
                }
    } else if (EPI == 1) {
        // P = exp(score) fp16, unnormalized. alpha = (1/sqrt(HID)) * log2(e).
        __half* cb = (__half*)Cp + bz * sC;
        #pragma unroll
        for (int mi = 0; mi < 4; mi++)
            #pragma unroll
            for (int ni = 0; ni < 4; ni++)
                #pragma unroll
                for (int h = 0; h < 2; h++) {
                    long long row = row0 + mi * 16 + h * 8;
                    int col = col0 + ni * 8;
                    float p0 = exp2f(alpha * acc[mi][ni][h * 2 + 0]);
                    float p1 = exp2f(alpha * acc[mi][ni][h * 2 + 1]);
                    *reinterpret_cast<__half2*>(cb + row * ldc + col) =
                        __half2(__float2half_rn(p0), __float2half_rn(p1));
                }
    } else {
        // PV: scale by per-row reciprocal row-sum.
        float* cb = (float*)Cp + bz * sC;
        const float* invb = g_inv + (size_t)bz * SEQ;
        #pragma unroll
        for (int mi = 0; mi < 4; mi++)
            #pragma unroll
            for (int h = 0; h < 2; h++) {
                long long row = row0 + mi * 16 + h * 8;
                float s = invb[row];
                #pragma unroll
                for (int ni = 0; ni < 4; ni++) {
                    int col = col0 + ni * 8;
                    float2 o;
                    o.x = s * acc[mi][ni][h * 2 + 0];
                    o.y = s * acc[mi][ni][h * 2 + 1];
                    *reinterpret_cast<float2*>(cb + row * ldc + col) = o;
                }
            }
    }
}

// ---------------- fp32 -> fp16 convert ----------------
__global__ __launch_bounds__(256)
void cvt_f32(const float* __restrict__ x, __half* __restrict__ h, int n4)
{
    int i = blockIdx.x * 256 + threadIdx.x;
    if (i >= n4) return;
    float4 v = reinterpret_cast<const float4*>(x)[i];
    reinterpret_cast<__half2*>(h)[2*i]   = __half2(__float2half_rn(v.x), __float2half_rn(v.y));
    reinterpret_cast<__half2*>(h)[2*i+1] = __half2(__float2half_rn(v.z), __float2half_rn(v.w));
}

// ---------------- row-sum of P -> reciprocal ----------------
__global__ __launch_bounds__(256)
void rowsum_kernel(const __half* __restrict__ P, float* __restrict__ inv)
{
    __shared__ float red[8];
    const __half2* p = reinterpret_cast<const __half2*>(P + (size_t)blockIdx.x * SEQ);
    const int tid = threadIdx.x;

    float s = 0.f;
    #pragma unroll
    for (int i = 0; i < 4; i++) {               // 1024 half2 / 256 threads
        float2 v = __half22float2(p[tid + i * 256]);
        s += v.x + v.y;
    }
    #pragma unroll
    for (int o = 16; o; o >>= 1) s += __shfl_xor_sync(0xffffffffu, s, o);
    if ((tid & 31) == 0) red[tid >> 5] = s;
    __syncthreads();
    if (tid == 0) {
        float t = red[0] + red[1] + red[2] + red[3] + red[4] + red[5] + red[6] + red[7];
        inv[blockIdx.x] = 1.f / t;
    }
}

// ---------------------------------------------------------------------------
extern "C" void kernel_launch(void* const* d_in, const int* in_sizes, int n_in,
                              void* d_out, int out_size)
{
    const float* X = (const float*)d_in[0];
    const float* W = (const float*)d_in[1];
    const float* b = (const float*)d_in[2];
    float* out = (float*)d_out;

    static bool attr_set = false;
    if (!attr_set) {
        cudaFuncSetAttribute(hmma_gemm<0>, cudaFuncAttributeMaxDynamicSharedMemorySize, SM_TOTAL);
        cudaFuncSetAttribute(hmma_gemm<1>, cudaFuncAttributeMaxDynamicSharedMemorySize, SM_TOTAL);
        cudaFuncSetAttribute(hmma_gemm<2>, cudaFuncAttributeMaxDynamicSharedMemorySize, SM_TOTAL);
        attr_set = true;
    }

    void *xh, *wh, *qh, *kh, *vTh, *ph, *inv;
    cudaGetSymbolAddress(&xh, g_xh);
    cudaGetSymbolAddress(&wh, g_wh);
    cudaGetSymbolAddress(&qh, g_qh);
    cudaGetSymbolAddress(&kh, g_kh);
    cudaGetSymbolAddress(&vTh, g_vTh);
    cudaGetSymbolAddress(&ph, g_ph);
    cudaGetSymbolAddress(&inv, g_inv);

    // 1) convert inputs to fp16
    cvt_f32<<<(TOK * HID / 4 + 255) / 256, 256>>>(X, (__half*)xh, TOK * HID / 4);
    cvt_f32<<<(NQKV * HID / 4 + 255) / 256, 256>>>(W, (__half*)wh, NQKV * HID / 4);

    // 2) QKV = X @ W^T + b  (M=8192, N=2304, K=768)
    hmma_gemm<0><<<dim3(NQKV / 128, TOK / 128, 1), 256, SM_TOTAL>>>(
        (__half*)xh, (__half*)wh,
        HID, HID, HID, 0LL, 0LL, b, 1.0f, nullptr, 0LL, 0LL);

    // 3) P = exp(Q @ K^T / sqrt(768))  per batch, fp16 unnormalized
    const float alpha = 1.44269504f * rsqrtf((float)HID);   // log2(e)/sqrt(HID)
    hmma_gemm<1><<<dim3(SEQ / 128, SEQ / 128, BATCH), 256, SM_TOTAL>>>(
        (__half*)qh, (__half*)kh,
        HID, HID, HID, (long long)SEQ * HID, (long long)SEQ * HID,
        nullptr, alpha, ph, SEQ, (long long)SEQ * SEQ);

    // 4) reciprocal row sums
    rowsum_kernel<<<BATCH * SEQ, 256>>>((const __half*)ph, (float*)inv);

    // 5) out = (P @ V) * inv_rowsum  per batch
    hmma_gemm<2><<<dim3(HID / 128, SEQ / 128, BATCH), 256, SM_TOTAL>>>(
        (__half*)ph, (__half*)vTh,
        SEQ, SEQ, SEQ, (long long)SEQ * SEQ, (long long)HID * SEQ,
        nullptr, 1.0f, out, HID, (long long)SEQ * HID);
}

// round 15
// speedup vs baseline: 5.0571x; 1.0386x over previous
#include <cuda_runtime.h>
#include <cuda_fp16.h>
#include <cstdint>
#include <math.h>

#define BATCH 4
#define SEQ   2048
#define HID   768
#define NQKV  (3*HID)
#define TOK   (BATCH*SEQ)   // 8192

// ---------------- scratch (device globals; allocation-free) ----------------
__device__ __align__(128) __half g_xh [(size_t)TOK*HID];
__device__ __align__(128) __half g_wh [(size_t)NQKV*HID];
__device__ __align__(128) __half g_qh [(size_t)TOK*HID];
__device__ __align__(128) __half g_kh [(size_t)TOK*HID];
__device__ __align__(128) __half g_vTh[(size_t)BATCH*HID*SEQ];
__device__ __align__(128) __half g_ph [(size_t)BATCH*SEQ*SEQ];   // unnormalized exp(scores), fp16
__device__ __align__(128) float  g_rsum[(size_t)BATCH*SEQ];      // row sums (atomic accum)

// ---------------- PTX helpers (sm_80-compatible only) ----------------
__device__ __forceinline__ uint32_t smem_u32(const void* p) {
    uint32_t a;
    asm("{ .reg .u64 t; cvta.to.shared.u64 t, %1; cvt.u32.u64 %0, t; }" : "=r"(a) : "l"(p));
    return a;
}
__device__ __forceinline__ void cp16(uint32_t dst, const void* src) {
    asm volatile("cp.async.cg.shared.global [%0], [%1], 16;" :: "r"(dst), "l"(src));
}
#define CP_COMMIT() asm volatile("cp.async.commit_group;" ::: "memory")
#define CP_WAIT1()  asm volatile("cp.async.wait_group 1;" ::: "memory")

__device__ __forceinline__ void ldm4(uint32_t* r, uint32_t addr) {
    asm volatile("ldmatrix.sync.aligned.m8n8.x4.shared.b16 {%0,%1,%2,%3}, [%4];"
                 : "=r"(r[0]), "=r"(r[1]), "=r"(r[2]), "=r"(r[3]) : "r"(addr));
}
__device__ __forceinline__ void mma16816(float* c, const uint32_t* a, const uint32_t* b) {
    asm volatile("mma.sync.aligned.m16n8k16.row.col.f32.f16.f16.f32 "
                 "{%0,%1,%2,%3}, {%4,%5,%6,%7}, {%8,%9}, {%0,%1,%2,%3};"
                 : "+f"(c[0]), "+f"(c[1]), "+f"(c[2]), "+f"(c[3])
                 : "r"(a[0]), "r"(a[1]), "r"(a[2]), "r"(a[3]), "r"(b[0]), "r"(b[1]));
}

// SW128-style swizzle for 128B rows: XOR off[9:7] into off[6:4].
__device__ __forceinline__ uint32_t swz(uint32_t off) {
    return off ^ ((off >> 3) & 0x70u);
}

// -------- HMMA GEMM: C[128x128] = A(MxK) · B(NxK)^T, pure fp16 --------------
// K-chunk = 64, swizzled 128B rows, 2 tiles/stage, 3 stages, 2 CTAs/SM.
#define ROWB    128
#define TILE_B  (128*ROWB)          // 16384
#define STAGE_B (2*TILE_B)          // 32768
#define NSTAGE  3
#define SM_TOTAL (NSTAGE*STAGE_B)   // 98304 (x2 CTAs = 196608)

// EPI: 0 = QKV (bias; Q,K fp16, V fp16 transposed)
//      1 = QK: P = exp(score) fp16 + per-row atomic partial sums into g_rsum
//      2 = PV: f32 out scaled by 1/g_rsum[row]
template<int EPI>
__global__ __launch_bounds__(256, 2)
void hmma_gemm(const __half* __restrict__ Ah, const __half* __restrict__ Bh,
               long long lda, long long ldb, int K,
               long long sA, long long sB,
               const float* __restrict__ bias, float alpha,
               void* __restrict__ Cp, long long ldc, long long sC)
{
    extern __shared__ char smem[];
    const uint32_t sbase = smem_u32(smem);
    const int tid = threadIdx.x;
    const int bx = blockIdx.x, by = blockIdx.y, bz = blockIdx.z;
    const int wid = tid >> 5, lane = tid & 31;
    const int wm = wid & 1;          // 2 warps in M (64 rows each)
    const int wn = wid >> 1;         // 4 warps in N (32 cols each)

    const __half* a_h = Ah + bz * sA + (long long)by * 128 * lda;
    const __half* b_h = Bh + bz * sB + (long long)bx * 128 * ldb;

    // per-thread ldmatrix lane addressing (pre-swizzle offsets)
    const int m_in = (lane & 7) + 8 * ((lane >> 3) & 1);
    const int kb_a = (lane >> 4) * 16;
    const int n_in = (lane & 7) + 8 * (lane >> 4);
    const int kb_b = ((lane >> 3) & 1) * 16;
    const uint32_t a_row_off = (uint32_t)((wm * 64 + m_in) * ROWB + kb_a);
    const uint32_t b_row_off = (uint32_t)((wn * 32 + n_in) * ROWB + kb_b);

    float acc[4][4][4];
    #pragma unroll
    for (int i = 0; i < 4; i++)
        #pragma unroll
        for (int j = 0; j < 4; j++)
            #pragma unroll
            for (int r = 0; r < 4; r++) acc[i][j][r] = 0.f;

    const int nch = K / 64;

    auto load_stage = [&](int c, int slot) {
        const uint32_t dbase = sbase + (uint32_t)slot * STAGE_B;
        const long long k0 = (long long)c * 64;
        #pragma unroll
        for (int t = 0; t < 2; t++) {
            const __half* src = (t == 0) ? a_h : b_h;
            const long long ld = (t == 0) ? lda : ldb;
            #pragma unroll
            for (int p = 0; p < 4; p++) {
                int idx = tid + p * 256;        // 0..1023
                int r = idx >> 3, ch = idx & 7;
                cp16(dbase + (uint32_t)t * TILE_B + swz((uint32_t)(r * ROWB + ch * 16)),
                     src + (long long)r * ld + k0 + ch * 8);
            }
        }
    };

    load_stage(0, 0); CP_COMMIT();
    load_stage(1, 1); CP_COMMIT();

    for (int c = 0; c < nch; c++) {
        CP_WAIT1();
        __syncthreads();
        if (c + 2 < nch) load_stage(c + 2, (c + 2) % NSTAGE);
        CP_COMMIT();

        const uint32_t st = sbase + (uint32_t)(c % NSTAGE) * STAGE_B;
        #pragma unroll
        for (int ks = 0; ks < 4; ks++) {
            uint32_t ah[4][4], bh[2][4];
            #pragma unroll
            for (int mi = 0; mi < 4; mi++) {
                uint32_t ao = a_row_off + (uint32_t)(mi * 16 * ROWB + ks * 32);
                ldm4(ah[mi], st + swz(ao));
            }
            #pragma unroll
            for (int nj = 0; nj < 2; nj++) {
                uint32_t bo = b_row_off + (uint32_t)(nj * 16 * ROWB + ks * 32);
                ldm4(bh[nj], st + TILE_B + swz(bo));
            }
            #pragma unroll
            for (int mi = 0; mi < 4; mi++)
                #pragma unroll
                for (int ni = 0; ni < 4; ni++)
                    mma16816(acc[mi][ni], ah[mi], &bh[ni >> 1][(ni & 1) * 2]);
        }
    }

    // ---------------- epilogue ----------------
    const int g = lane >> 2, t4 = lane & 3;
    const int row0 = by * 128 + wm * 64 + g;
    const int col0 = bx * 128 + wn * 32 + t4 * 2;

    if (EPI == 0) {
        const float* bias_p = bias;
        const int seg = (bx * 128) / HID;          // 0=Q, 1=K, 2=V (tile never straddles)
        #pragma unroll
        for (int mi = 0; mi < 4; mi++)
            #pragma unroll
            for (int ni = 0; ni < 4; ni++)
                #pragma unroll
                for (int h = 0; h < 2; h++) {
                    long long row = row0 + mi * 16 + h * 8;
                    int col = col0 + ni * 8;
                    float v0 = acc[mi][ni][h * 2 + 0] + bias_p[col];
                    float v1 = acc[mi][ni][h * 2 + 1] + bias_p[col + 1];
                    __half h0 = __float2half_rn(v0);
                    __half h1 = __float2half_rn(v1);
                    if (seg == 0) {
                        *reinterpret_cast<__half2*>(g_qh + row * HID + col) = __half2(h0, h1);
                    } else if (seg == 1) {
                        *reinterpret_cast<__half2*>(g_kh + row * HID + (col - HID)) = __half2(h0, h1);
                    } else {
                        int hh = col - 2 * HID;
                        int b = (int)(row >> 11), s = (int)(row & 2047);
                        size_t o0 = ((size_t)b * HID + hh) * SEQ + s;
                        g_vTh[o0] = h0;
                        g_vTh[o0 + SEQ] = h1;
                    }
                }
    } else if (EPI == 1) {
        // P = exp(score) fp16 (alpha = log2e/sqrt(HID)), plus row-sum partials.
        __half* cb = (__half*)Cp + bz * sC;
        float* rs = g_rsum + (size_t)bz * SEQ;
        #pragma unroll
        for (int mi = 0; mi < 4; mi++)
            #pragma unroll
            for (int h = 0; h < 2; h++) {
                long long row = row0 + mi * 16 + h * 8;
                float part = 0.f;
                #pragma unroll
                for (int ni = 0; ni < 4; ni++) {
                    int col = col0 + ni * 8;
                    float p0 = exp2f(alpha * acc[mi][ni][h * 2 + 0]);
                    float p1 = exp2f(alpha * acc[mi][ni][h * 2 + 1]);
                    part += p0 + p1;
                    *reinterpret_cast<__half2*>(cb + row * ldc + col) =
                        __half2(__float2half_rn(p0), __float2half_rn(p1));
                }
                // reduce across the 4 lanes sharing this row (lane bits 0..1 = t4)
                part += __shfl_xor_sync(0xffffffffu, part, 1);
                part += __shfl_xor_sync(0xffffffffu, part, 2);
                if (t4 == 0) atomicAdd(rs + row, part);
            }
    } else {
        // PV: scale by reciprocal row-sum.
        float* cb = (float*)Cp + bz * sC;
        const float* rsb = g_rsum + (size_t)bz * SEQ;
        #pragma unroll
        for (int mi = 0; mi < 4; mi++)
            #pragma unroll
            for (int h = 0; h < 2; h++) {
                long long row = row0 + mi * 16 + h * 8;
                float s = 1.f / rsb[row];
                #pragma unroll
                for (int ni = 0; ni < 4; ni++) {
                    int col = col0 + ni * 8;
                    float2 o;
                    o.x = s * acc[mi][ni][h * 2 + 0];
                    o.y = s * acc[mi][ni][h * 2 + 1];
                    *reinterpret_cast<float2*>(cb + row * ldc + col) = o;
                }
            }
    }
}

// ---------------- zero row-sum accumulator (graph replays need re-zero) ----
__global__ __launch_bounds__(256)
void zero_rsum(float* __restrict__ rs)
{
    rs[blockIdx.x * 256 + threadIdx.x] = 0.f;
}

// ---------------- fp32 -> fp16 convert (X and W in one launch) -------------
__global__ __launch_bounds__(256)
void cvt_all(const float* __restrict__ X, const float* __restrict__ W,
             __half* __restrict__ xh, __half* __restrict__ wh,
             int nX4, int nW4)
{
    int i = blockIdx.x * 256 + threadIdx.x;
    const float* src;
    __half* dst;
    int j;
    if (i < nX4)            { src = X; dst = xh; j = i; }
    else if (i < nX4 + nW4) { src = W; dst = wh; j = i - nX4; }
    else return;
    float4 v = reinterpret_cast<const float4*>(src)[j];
    reinterpret_cast<__half2*>(dst)[2*j]   = __half2(__float2half_rn(v.x), __float2half_rn(v.y));
    reinterpret_cast<__half2*>(dst)[2*j+1] = __half2(__float2half_rn(v.z), __float2half_rn(v.w));
}

// ---------------------------------------------------------------------------
extern "C" void kernel_launch(void* const* d_in, const int* in_sizes, int n_in,
                              void* d_out, int out_size)
{
    const float* X = (const float*)d_in[0];
    const float* W = (const float*)d_in[1];
    const float* b = (const float*)d_in[2];
    float* out = (float*)d_out;

    static bool attr_set = false;
    if (!attr_set) {
        cudaFuncSetAttribute(hmma_gemm<0>, cudaFuncAttributeMaxDynamicSharedMemorySize, SM_TOTAL);
        cudaFuncSetAttribute(hmma_gemm<1>, cudaFuncAttributeMaxDynamicSharedMemorySize, SM_TOTAL);
        cudaFuncSetAttribute(hmma_gemm<2>, cudaFuncAttributeMaxDynamicSharedMemorySize, SM_TOTAL);
        attr_set = true;
    }

    void *xh, *wh, *qh, *kh, *vTh, *ph, *rs;
    cudaGetSymbolAddress(&xh, g_xh);
    cudaGetSymbolAddress(&wh, g_wh);
    cudaGetSymbolAddress(&qh, g_qh);
    cudaGetSymbolAddress(&kh, g_kh);
    cudaGetSymbolAddress(&vTh, g_vTh);
    cudaGetSymbolAddress(&ph, g_ph);
    cudaGetSymbolAddress(&rs, g_rsum);

    const int nX4 = TOK * HID / 4;      // 1,572,864
    const int nW4 = NQKV * HID / 4;     //   442,368

    // 1) zero row-sum accumulator + convert inputs to fp16
    zero_rsum<<<TOK / 256, 256>>>((float*)rs);
    cvt_all<<<(nX4 + nW4 + 255) / 256, 256>>>(X, W, (__half*)xh, (__half*)wh, nX4, nW4);

    // 2) QKV = X @ W^T + b  (M=8192, N=2304, K=768)
    hmma_gemm<0><<<dim3(NQKV / 128, TOK / 128, 1), 256, SM_TOTAL>>>(
        (__half*)xh, (__half*)wh,
        HID, HID, HID, 0LL, 0LL, b, 1.0f, nullptr, 0LL, 0LL);

    // 3) P = exp(Q @ K^T / sqrt(768)) fp16 + row sums via atomics
    const float alpha = 1.44269504f * rsqrtf((float)HID);   // log2(e)/sqrt(HID)
    hmma_gemm<1><<<dim3(SEQ / 128, SEQ / 128, BATCH), 256, SM_TOTAL>>>(
        (__half*)qh, (__half*)kh,
        HID, HID, HID, (long long)SEQ * HID, (long long)SEQ * HID,
        nullptr, alpha, ph, SEQ, (long long)SEQ * SEQ);

    // 4) out = (P @ V) / rowsum  per batch
    hmma_gemm<2><<<dim3(HID / 128, SEQ / 128, BATCH), 256, SM_TOTAL>>>(
        (__half*)ph, (__half*)vTh,
        SEQ, SEQ, SEQ, (long long)SEQ * SEQ, (long long)HID * SEQ,
        nullptr, 1.0f, out, HID, (long long)SEQ * HID);
}